// round 1
// baseline (speedup 1.0000x reference)
#include <cuda_runtime.h>
#include <math.h>

// Problem constants (fixed by the reference):
// B=2, S=2048, D=1024, H=16, DH=64, INNER=1024
#define BB   2
#define SS   2048
#define DD   1024
#define HH   16
#define DHD  64
#define MROWS (BB * SS)   // 4096 token rows

// Scratch (static device globals -- no allocations allowed)
__device__ float g_q [(size_t)MROWS * DD];        // 16 MB : q projection (normalized in place)
__device__ float g_kv[(size_t)MROWS * 2 * DD];    // 32 MB : [k | v] projection (k normalized in place)
__device__ float g_o [(size_t)MROWS * DD];        // 16 MB : attention output before w_out

// ---------------------------------------------------------------------------
// Classic 128x128x8 SGEMM, 256 threads, 8x8 microtile, C = A[M,K] @ B[K,N] (+bias)
// M is implied by grid.y * 128. All dims here are multiples of 128.
// ---------------------------------------------------------------------------
__global__ __launch_bounds__(256) void sgemm128(
    const float* __restrict__ A, const float* __restrict__ B,
    float* __restrict__ C, int N, int K, const float* __restrict__ bias)
{
    __shared__ float As[8][128];   // transposed: As[k][m]
    __shared__ float Bs[8][128];   // Bs[k][n]

    const int tid = threadIdx.x;
    const int bm  = blockIdx.y * 128;
    const int bn  = blockIdx.x * 128;
    const int tx  = tid & 15;
    const int ty  = tid >> 4;

    const int aRow = tid >> 1;            // 0..127
    const int aCol = (tid & 1) * 4;       // 0 or 4
    const int bRow = tid >> 5;            // 0..7
    const int bCol = (tid & 31) * 4;      // 0..124

    float acc[8][8];
#pragma unroll
    for (int i = 0; i < 8; i++)
#pragma unroll
        for (int j = 0; j < 8; j++) acc[i][j] = 0.f;

    const float* Aptr = A + (size_t)(bm + aRow) * K + aCol;
    const float* Bptr = B + (size_t)bRow * N + bn + bCol;

    for (int kt = 0; kt < K; kt += 8) {
        float4 a4 = *(const float4*)(Aptr + kt);
        As[aCol + 0][aRow] = a4.x;
        As[aCol + 1][aRow] = a4.y;
        As[aCol + 2][aRow] = a4.z;
        As[aCol + 3][aRow] = a4.w;
        *(float4*)&Bs[bRow][bCol] = *(const float4*)(Bptr + (size_t)kt * N);
        __syncthreads();

#pragma unroll
        for (int k = 0; k < 8; k++) {
            float ra[8], rb[8];
            *(float4*)&ra[0] = *(float4*)&As[k][ty * 4];
            *(float4*)&ra[4] = *(float4*)&As[k][64 + ty * 4];
            *(float4*)&rb[0] = *(float4*)&Bs[k][tx * 4];
            *(float4*)&rb[4] = *(float4*)&Bs[k][64 + tx * 4];
#pragma unroll
            for (int i = 0; i < 8; i++)
#pragma unroll
                for (int j = 0; j < 8; j++)
                    acc[i][j] += ra[i] * rb[j];
        }
        __syncthreads();
    }

#pragma unroll
    for (int i = 0; i < 8; i++) {
        int row = bm + ((i < 4) ? (ty * 4 + i) : (64 + ty * 4 + (i - 4)));
#pragma unroll
        for (int jj = 0; jj < 2; jj++) {
            int col = bn + ((jj == 0) ? (tx * 4) : (64 + tx * 4));
            float4 v;
            v.x = acc[i][jj * 4 + 0];
            v.y = acc[i][jj * 4 + 1];
            v.z = acc[i][jj * 4 + 2];
            v.w = acc[i][jj * 4 + 3];
            if (bias) {
                v.x += bias[col + 0];
                v.y += bias[col + 1];
                v.z += bias[col + 2];
                v.w += bias[col + 3];
            }
            *(float4*)(C + (size_t)row * N + col) = v;
        }
    }
}

// ---------------------------------------------------------------------------
// L2-normalize per (b,s,h) head-row of 64. One warp per row, 2 elems/lane.
// q rows additionally multiplied by exp(scale[h]). k rows just normalized.
// ---------------------------------------------------------------------------
__global__ void normalize_kernel(float* __restrict__ q, float* __restrict__ kv,
                                 const float* __restrict__ scale)
{
    const int warp  = (blockIdx.x * blockDim.x + threadIdx.x) >> 5;
    const int lane  = threadIdx.x & 31;
    const int total = MROWS * HH;               // 65536 head-rows per tensor
    const bool isQ  = warp < total;
    const int  r    = isQ ? warp : warp - total;
    if (r >= total) return;
    const int bs = r >> 4;                      // token index
    const int h  = r & 15;

    float* ptr = isQ ? (q  + (size_t)bs * DD       + h * DHD)
                     : (kv + (size_t)bs * (2 * DD) + h * DHD);

    float2 v = *(float2*)(ptr + lane * 2);
    float ss = v.x * v.x + v.y * v.y;
#pragma unroll
    for (int m = 16; m > 0; m >>= 1) ss += __shfl_xor_sync(0xffffffffu, ss, m);

    float nrm = sqrtf(ss);
    float f   = 1.f / fmaxf(nrm, 1e-12f);
    if (isQ) f *= expf(scale[h]);
    v.x *= f;
    v.y *= f;
    *(float2*)(ptr + lane * 2) = v;
}

// ---------------------------------------------------------------------------
// Flash attention fp32, 64x64 Q-tile per block, 256 threads (16x16 grid, 4x4
// microtiles). Logits are bounded by exp(scale) ~= 0.0455 (L2-normalized q,k),
// so softmax needs no running max: exp(s) directly is exact and stable.
// Smem layout (dynamic, 69632 B): Qt[64][68] ([d][i]), Kt[64][68] ([d][j]),
// Vs[64][68] ([j][c]), Ps[64][68] ([i][j]).
// ---------------------------------------------------------------------------
#define FLASH_SMEM (4 * 64 * 68 * 4)

__global__ __launch_bounds__(256) void flash_kernel(
    const float* __restrict__ q, const float* __restrict__ kv, float* __restrict__ o)
{
    extern __shared__ float smem[];
    float (*Qt)[68] = (float (*)[68])(smem);
    float (*Kt)[68] = (float (*)[68])(smem + 64 * 68);
    float (*Vs)[68] = (float (*)[68])(smem + 2 * 64 * 68);
    float (*Ps)[68] = (float (*)[68])(smem + 3 * 64 * 68);

    const int qt = blockIdx.x;   // 0..31
    const int h  = blockIdx.y;   // 0..15
    const int b  = blockIdx.z;   // 0..1
    const int tid = threadIdx.x;
    const int tx = tid & 15, ty = tid >> 4;

    const float* qbase = q  + ((size_t)(b * SS) + qt * 64) * DD + h * DHD;
    const float* kbase = kv + (size_t)(b * SS) * (2 * DD) + h * DHD;
    const float* vbase = kbase + DD;

    // Load Q tile transposed: Qt[d][i] = q[i][d]
    {
        const int r  = tid >> 2;          // 0..63 (q row within tile)
        const int c0 = (tid & 3) * 16;    // d chunk start
#pragma unroll
        for (int u = 0; u < 4; u++) {
            float4 qv = *(const float4*)(qbase + (size_t)r * DD + c0 + u * 4);
            Qt[c0 + u * 4 + 0][r] = qv.x;
            Qt[c0 + u * 4 + 1][r] = qv.y;
            Qt[c0 + u * 4 + 2][r] = qv.z;
            Qt[c0 + u * 4 + 3][r] = qv.w;
        }
    }

    float l[4];
    float oacc[4][4];
#pragma unroll
    for (int i = 0; i < 4; i++) {
        l[i] = 0.f;
#pragma unroll
        for (int c = 0; c < 4; c++) oacc[i][c] = 0.f;
    }

    for (int jt = 0; jt < SS / 64; jt++) {
        __syncthreads();   // protect Kt/Vs from previous iteration readers
        // Load K tile transposed (Kt[d][j]) and V tile (Vs[j][c])
        {
            const int r  = tid >> 2;
            const int c0 = (tid & 3) * 16;
            const float* krow = kbase + (size_t)(jt * 64 + r) * (2 * DD);
            const float* vrow = vbase + (size_t)(jt * 64 + r) * (2 * DD);
#pragma unroll
            for (int u = 0; u < 4; u++) {
                float4 kk = *(const float4*)(krow + c0 + u * 4);
                Kt[c0 + u * 4 + 0][r] = kk.x;
                Kt[c0 + u * 4 + 1][r] = kk.y;
                Kt[c0 + u * 4 + 2][r] = kk.z;
                Kt[c0 + u * 4 + 3][r] = kk.w;
                *(float4*)&Vs[r][c0 + u * 4] = *(const float4*)(vrow + c0 + u * 4);
            }
        }
        __syncthreads();

        // GEMM1: S[i][j] = sum_d Qt[d][i] * Kt[d][j]
        float s[4][4];
#pragma unroll
        for (int i = 0; i < 4; i++)
#pragma unroll
            for (int j = 0; j < 4; j++) s[i][j] = 0.f;

#pragma unroll 8
        for (int d = 0; d < 64; d++) {
            float ra[4], rb[4];
            *(float4*)ra = *(float4*)&Qt[d][ty * 4];
            *(float4*)rb = *(float4*)&Kt[d][tx * 4];
#pragma unroll
            for (int i = 0; i < 4; i++)
#pragma unroll
                for (int j = 0; j < 4; j++)
                    s[i][j] += ra[i] * rb[j];
        }

        // Max-free softmax numerator: |s| <= exp(scale) ~ 0.0455, exp is safe.
#pragma unroll
        for (int i = 0; i < 4; i++) {
            float sum = 0.f;
#pragma unroll
            for (int j = 0; j < 4; j++) {
                float p = expf(s[i][j]);
                Ps[ty * 4 + i][tx * 4 + j] = p;
                sum += p;
            }
#pragma unroll
            for (int mk = 1; mk < 16; mk <<= 1)
                sum += __shfl_xor_sync(0xffffffffu, sum, mk);
            l[i] += sum;
        }
        __syncthreads();

        // GEMM2: O[i][c] += sum_j Ps[i][j] * Vs[j][c]
#pragma unroll 8
        for (int j = 0; j < 64; j++) {
            float pa[4], vb[4];
#pragma unroll
            for (int i = 0; i < 4; i++) pa[i] = Ps[ty * 4 + i][j];
            *(float4*)vb = *(float4*)&Vs[j][tx * 4];
#pragma unroll
            for (int i = 0; i < 4; i++)
#pragma unroll
                for (int c = 0; c < 4; c++)
                    oacc[i][c] += pa[i] * vb[c];
        }
    }

    // Epilogue: divide by softmax denominator, store to g_o in [token][h*64+c] layout
    float* obase = o + ((size_t)(b * SS) + qt * 64) * DD + h * DHD;
#pragma unroll
    for (int i = 0; i < 4; i++) {
        float inv = 1.f / l[i];
        float4 v;
        v.x = oacc[i][0] * inv;
        v.y = oacc[i][1] * inv;
        v.z = oacc[i][2] * inv;
        v.w = oacc[i][3] * inv;
        *(float4*)(obase + (size_t)(ty * 4 + i) * DD + tx * 4) = v;
    }
}

// ---------------------------------------------------------------------------
extern "C" void kernel_launch(void* const* d_in, const int* in_sizes, int n_in,
                              void* d_out, int out_size)
{
    const float* x     = (const float*)d_in[0];
    const float* w_q   = (const float*)d_in[1];
    const float* w_kv  = (const float*)d_in[2];
    const float* w_out = (const float*)d_in[3];
    const float* b_out = (const float*)d_in[4];
    const float* scale = (const float*)d_in[5];
    float* out = (float*)d_out;

    float *pq, *pkv, *po;
    cudaGetSymbolAddress((void**)&pq,  g_q);
    cudaGetSymbolAddress((void**)&pkv, g_kv);
    cudaGetSymbolAddress((void**)&po,  g_o);

    cudaFuncSetAttribute(flash_kernel, cudaFuncAttributeMaxDynamicSharedMemorySize, FLASH_SMEM);

    dim3 blk(256);
    // q = x @ w_q            [4096,1024] @ [1024,1024]
    sgemm128<<<dim3(DD / 128, MROWS / 128), blk>>>(x, w_q, pq, DD, DD, nullptr);
    // kv = x @ w_kv          [4096,1024] @ [1024,2048]
    sgemm128<<<dim3(2 * DD / 128, MROWS / 128), blk>>>(x, w_kv, pkv, 2 * DD, DD, nullptr);
    // L2-normalize q (x exp(scale)) and k per head-row
    normalize_kernel<<<(2 * MROWS * HH) / 8, 256>>>(pq, pkv, scale);
    // attention -> g_o
    flash_kernel<<<dim3(SS / 64, HH, BB), 256, FLASH_SMEM>>>(pq, pkv, po);
    // out = g_o @ w_out + b_out
    sgemm128<<<dim3(DD / 128, MROWS / 128), blk>>>(po, w_out, out, DD, DD, b_out);
}

// round 2
// speedup vs baseline: 1.0008x; 1.0008x over previous
#include <cuda_runtime.h>
#include <math.h>

// Problem constants (fixed by the reference):
// B=2, S=2048, D=1024, H=16, DH=64, INNER=1024
#define BB   2
#define SS   2048
#define DD   1024
#define HH   16
#define DHD  64
#define MROWS (BB * SS)   // 4096 token rows

// Scratch (static device globals -- no allocations allowed)
__device__ float g_q [(size_t)MROWS * DD];        // 16 MB : q projection (normalized in place)
__device__ float g_kv[(size_t)MROWS * 2 * DD];    // 32 MB : [k | v] projection (k normalized in place)
__device__ float g_o [(size_t)MROWS * DD];        // 16 MB : attention output before w_out

// ---------------------------------------------------------------------------
// Classic 128x128x8 SGEMM, 256 threads, 8x8 microtile, C = A[M,K] @ B[K,N] (+bias)
// M is implied by grid.y * 128. All dims here are multiples of 128.
// ---------------------------------------------------------------------------
__global__ __launch_bounds__(256) void sgemm128(
    const float* __restrict__ A, const float* __restrict__ B,
    float* __restrict__ C, int N, int K, const float* __restrict__ bias)
{
    __shared__ float As[8][128];   // transposed: As[k][m]
    __shared__ float Bs[8][128];   // Bs[k][n]

    const int tid = threadIdx.x;
    const int bm  = blockIdx.y * 128;
    const int bn  = blockIdx.x * 128;
    const int tx  = tid & 15;
    const int ty  = tid >> 4;

    const int aRow = tid >> 1;            // 0..127
    const int aCol = (tid & 1) * 4;       // 0 or 4
    const int bRow = tid >> 5;            // 0..7
    const int bCol = (tid & 31) * 4;      // 0..124

    float acc[8][8];
#pragma unroll
    for (int i = 0; i < 8; i++)
#pragma unroll
        for (int j = 0; j < 8; j++) acc[i][j] = 0.f;

    const float* Aptr = A + (size_t)(bm + aRow) * K + aCol;
    const float* Bptr = B + (size_t)bRow * N + bn + bCol;

    for (int kt = 0; kt < K; kt += 8) {
        float4 a4 = *(const float4*)(Aptr + kt);
        As[aCol + 0][aRow] = a4.x;
        As[aCol + 1][aRow] = a4.y;
        As[aCol + 2][aRow] = a4.z;
        As[aCol + 3][aRow] = a4.w;
        *(float4*)&Bs[bRow][bCol] = *(const float4*)(Bptr + (size_t)kt * N);
        __syncthreads();

#pragma unroll
        for (int k = 0; k < 8; k++) {
            float ra[8], rb[8];
            *(float4*)&ra[0] = *(float4*)&As[k][ty * 4];
            *(float4*)&ra[4] = *(float4*)&As[k][64 + ty * 4];
            *(float4*)&rb[0] = *(float4*)&Bs[k][tx * 4];
            *(float4*)&rb[4] = *(float4*)&Bs[k][64 + tx * 4];
#pragma unroll
            for (int i = 0; i < 8; i++)
#pragma unroll
                for (int j = 0; j < 8; j++)
                    acc[i][j] += ra[i] * rb[j];
        }
        __syncthreads();
    }

#pragma unroll
    for (int i = 0; i < 8; i++) {
        int row = bm + ((i < 4) ? (ty * 4 + i) : (64 + ty * 4 + (i - 4)));
#pragma unroll
        for (int jj = 0; jj < 2; jj++) {
            int col = bn + ((jj == 0) ? (tx * 4) : (64 + tx * 4));
            float4 v;
            v.x = acc[i][jj * 4 + 0];
            v.y = acc[i][jj * 4 + 1];
            v.z = acc[i][jj * 4 + 2];
            v.w = acc[i][jj * 4 + 3];
            if (bias) {
                v.x += bias[col + 0];
                v.y += bias[col + 1];
                v.z += bias[col + 2];
                v.w += bias[col + 3];
            }
            *(float4*)(C + (size_t)row * N + col) = v;
        }
    }
}

// ---------------------------------------------------------------------------
// L2-normalize per (b,s,h) head-row of 64. One warp per row, 2 elems/lane.
// q rows additionally multiplied by exp(scale[h]). k rows just normalized.
// ---------------------------------------------------------------------------
__global__ void normalize_kernel(float* __restrict__ q, float* __restrict__ kv,
                                 const float* __restrict__ scale)
{
    const int warp  = (blockIdx.x * blockDim.x + threadIdx.x) >> 5;
    const int lane  = threadIdx.x & 31;
    const int total = MROWS * HH;               // 65536 head-rows per tensor
    const bool isQ  = warp < total;
    const int  r    = isQ ? warp : warp - total;
    if (r >= total) return;
    const int bs = r >> 4;                      // token index
    const int h  = r & 15;

    float* ptr = isQ ? (q  + (size_t)bs * DD       + h * DHD)
                     : (kv + (size_t)bs * (2 * DD) + h * DHD);

    float2 v = *(float2*)(ptr + lane * 2);
    float ss = v.x * v.x + v.y * v.y;
#pragma unroll
    for (int m = 16; m > 0; m >>= 1) ss += __shfl_xor_sync(0xffffffffu, ss, m);

    float nrm = sqrtf(ss);
    float f   = 1.f / fmaxf(nrm, 1e-12f);
    if (isQ) f *= expf(scale[h]);
    v.x *= f;
    v.y *= f;
    *(float2*)(ptr + lane * 2) = v;
}

// ---------------------------------------------------------------------------
// Flash attention fp32, 64x64 Q-tile per block, 256 threads (16x16 grid, 4x4
// microtiles). Logits are bounded by exp(scale) ~= 0.0455 (L2-normalized q,k),
// so softmax needs no running max: exp(s) directly is exact and stable.
// Smem layout (dynamic, 69632 B): Qt[64][68] ([d][i]), Kt[64][68] ([d][j]),
// Vs[64][68] ([j][c]), Ps[64][68] ([i][j]).
// ---------------------------------------------------------------------------
#define FLASH_SMEM (4 * 64 * 68 * 4)

__global__ __launch_bounds__(256) void flash_kernel(
    const float* __restrict__ q, const float* __restrict__ kv, float* __restrict__ o)
{
    extern __shared__ float smem[];
    float (*Qt)[68] = (float (*)[68])(smem);
    float (*Kt)[68] = (float (*)[68])(smem + 64 * 68);
    float (*Vs)[68] = (float (*)[68])(smem + 2 * 64 * 68);
    float (*Ps)[68] = (float (*)[68])(smem + 3 * 64 * 68);

    const int qt = blockIdx.x;   // 0..31
    const int h  = blockIdx.y;   // 0..15
    const int b  = blockIdx.z;   // 0..1
    const int tid = threadIdx.x;
    const int tx = tid & 15, ty = tid >> 4;

    const float* qbase = q  + ((size_t)(b * SS) + qt * 64) * DD + h * DHD;
    const float* kbase = kv + (size_t)(b * SS) * (2 * DD) + h * DHD;
    const float* vbase = kbase + DD;

    // Load Q tile transposed: Qt[d][i] = q[i][d]
    {
        const int r  = tid >> 2;          // 0..63 (q row within tile)
        const int c0 = (tid & 3) * 16;    // d chunk start
#pragma unroll
        for (int u = 0; u < 4; u++) {
            float4 qv = *(const float4*)(qbase + (size_t)r * DD + c0 + u * 4);
            Qt[c0 + u * 4 + 0][r] = qv.x;
            Qt[c0 + u * 4 + 1][r] = qv.y;
            Qt[c0 + u * 4 + 2][r] = qv.z;
            Qt[c0 + u * 4 + 3][r] = qv.w;
        }
    }

    float l[4];
    float oacc[4][4];
#pragma unroll
    for (int i = 0; i < 4; i++) {
        l[i] = 0.f;
#pragma unroll
        for (int c = 0; c < 4; c++) oacc[i][c] = 0.f;
    }

    for (int jt = 0; jt < SS / 64; jt++) {
        __syncthreads();   // protect Kt/Vs from previous iteration readers
        // Load K tile transposed (Kt[d][j]) and V tile (Vs[j][c])
        {
            const int r  = tid >> 2;
            const int c0 = (tid & 3) * 16;
            const float* krow = kbase + (size_t)(jt * 64 + r) * (2 * DD);
            const float* vrow = vbase + (size_t)(jt * 64 + r) * (2 * DD);
#pragma unroll
            for (int u = 0; u < 4; u++) {
                float4 kk = *(const float4*)(krow + c0 + u * 4);
                Kt[c0 + u * 4 + 0][r] = kk.x;
                Kt[c0 + u * 4 + 1][r] = kk.y;
                Kt[c0 + u * 4 + 2][r] = kk.z;
                Kt[c0 + u * 4 + 3][r] = kk.w;
                *(float4*)&Vs[r][c0 + u * 4] = *(const float4*)(vrow + c0 + u * 4);
            }
        }
        __syncthreads();

        // GEMM1: S[i][j] = sum_d Qt[d][i] * Kt[d][j]
        float s[4][4];
#pragma unroll
        for (int i = 0; i < 4; i++)
#pragma unroll
            for (int j = 0; j < 4; j++) s[i][j] = 0.f;

#pragma unroll 8
        for (int d = 0; d < 64; d++) {
            float ra[4], rb[4];
            *(float4*)ra = *(float4*)&Qt[d][ty * 4];
            *(float4*)rb = *(float4*)&Kt[d][tx * 4];
#pragma unroll
            for (int i = 0; i < 4; i++)
#pragma unroll
                for (int j = 0; j < 4; j++)
                    s[i][j] += ra[i] * rb[j];
        }

        // Max-free softmax numerator: |s| <= exp(scale) ~ 0.0455, exp is safe.
#pragma unroll
        for (int i = 0; i < 4; i++) {
            float sum = 0.f;
#pragma unroll
            for (int j = 0; j < 4; j++) {
                float p = expf(s[i][j]);
                Ps[ty * 4 + i][tx * 4 + j] = p;
                sum += p;
            }
#pragma unroll
            for (int mk = 1; mk < 16; mk <<= 1)
                sum += __shfl_xor_sync(0xffffffffu, sum, mk);
            l[i] += sum;
        }
        __syncthreads();

        // GEMM2: O[i][c] += sum_j Ps[i][j] * Vs[j][c]
#pragma unroll 8
        for (int j = 0; j < 64; j++) {
            float pa[4], vb[4];
#pragma unroll
            for (int i = 0; i < 4; i++) pa[i] = Ps[ty * 4 + i][j];
            *(float4*)vb = *(float4*)&Vs[j][tx * 4];
#pragma unroll
            for (int i = 0; i < 4; i++)
#pragma unroll
                for (int c = 0; c < 4; c++)
                    oacc[i][c] += pa[i] * vb[c];
        }
    }

    // Epilogue: divide by softmax denominator, store to g_o in [token][h*64+c] layout
    float* obase = o + ((size_t)(b * SS) + qt * 64) * DD + h * DHD;
#pragma unroll
    for (int i = 0; i < 4; i++) {
        float inv = 1.f / l[i];
        float4 v;
        v.x = oacc[i][0] * inv;
        v.y = oacc[i][1] * inv;
        v.z = oacc[i][2] * inv;
        v.w = oacc[i][3] * inv;
        *(float4*)(obase + (size_t)(ty * 4 + i) * DD + tx * 4) = v;
    }
}

// ---------------------------------------------------------------------------
extern "C" void kernel_launch(void* const* d_in, const int* in_sizes, int n_in,
                              void* d_out, int out_size)
{
    const float* x     = (const float*)d_in[0];
    const float* w_q   = (const float*)d_in[1];
    const float* w_kv  = (const float*)d_in[2];
    const float* w_out = (const float*)d_in[3];
    const float* b_out = (const float*)d_in[4];
    const float* scale = (const float*)d_in[5];
    float* out = (float*)d_out;

    float *pq, *pkv, *po;
    cudaGetSymbolAddress((void**)&pq,  g_q);
    cudaGetSymbolAddress((void**)&pkv, g_kv);
    cudaGetSymbolAddress((void**)&po,  g_o);

    cudaFuncSetAttribute(flash_kernel, cudaFuncAttributeMaxDynamicSharedMemorySize, FLASH_SMEM);

    dim3 blk(256);
    // q = x @ w_q            [4096,1024] @ [1024,1024]
    sgemm128<<<dim3(DD / 128, MROWS / 128), blk>>>(x, w_q, pq, DD, DD, nullptr);
    // kv = x @ w_kv          [4096,1024] @ [1024,2048]
    sgemm128<<<dim3(2 * DD / 128, MROWS / 128), blk>>>(x, w_kv, pkv, 2 * DD, DD, nullptr);
    // L2-normalize q (x exp(scale)) and k per head-row
    normalize_kernel<<<(2 * MROWS * HH) / 8, 256>>>(pq, pkv, scale);
    // attention -> g_o
    flash_kernel<<<dim3(SS / 64, HH, BB), 256, FLASH_SMEM>>>(pq, pkv, po);
    // out = g_o @ w_out + b_out
    sgemm128<<<dim3(DD / 128, MROWS / 128), blk>>>(po, w_out, out, DD, DD, b_out);
}

// round 4
// speedup vs baseline: 1.3863x; 1.3853x over previous
#include <cuda_runtime.h>
#include <math.h>
#include <stdint.h>

// Problem constants: B=2, S=2048, D=1024, H=16, DH=64, INNER=1024
#define BB   2
#define SS   2048
#define DD   1024
#define HH   16
#define DHD  64
#define MROWS (BB * SS)   // 4096 token rows

// Scratch (static device globals -- no allocations allowed)
__device__ float g_x  [(size_t)MROWS * DD];         // tf32-rounded x
__device__ float g_q  [(size_t)MROWS * DD];         // q projection (normalized in place)
__device__ float g_kv [(size_t)MROWS * 2 * DD];     // [k | v] projection
__device__ float g_o  [(size_t)MROWS * DD];         // attention output before w_out
__device__ float g_wq [(size_t)DD * DD];            // tf32-rounded w_q
__device__ float g_wkv[(size_t)DD * 2 * DD];        // tf32-rounded w_kv
__device__ float g_wo [(size_t)DD * DD];            // tf32-rounded w_out

// ---------------------------------------------------------------------------
// helpers
// ---------------------------------------------------------------------------
__device__ __forceinline__ uint32_t smem_u32(const void* p) {
    uint32_t a;
    asm("{ .reg .u64 t; cvta.to.shared.u64 t, %1; cvt.u32.u64 %0, t; }" : "=r"(a) : "l"(p));
    return a;
}

__device__ __forceinline__ float tf32r(float x) {
    uint32_t u;
    asm("cvt.rna.tf32.f32 %0, %1;" : "=r"(u) : "f"(x));
    return __uint_as_float(u);
}

__device__ __forceinline__ void cp16(uint32_t dst, const void* src) {
    asm volatile("cp.async.cg.shared.global [%0], [%1], 16;" :: "r"(dst), "l"(src));
}
__device__ __forceinline__ void cp_commit() {
    asm volatile("cp.async.commit_group;" ::: "memory");
}
__device__ __forceinline__ void cp_wait1() {
    asm volatile("cp.async.wait_group 1;" ::: "memory");
}
__device__ __forceinline__ void cp_wait0() {
    asm volatile("cp.async.wait_group 0;" ::: "memory");
}

__device__ __forceinline__ void mma_tf32(float* d, const uint32_t* a, const uint32_t* b) {
    asm volatile(
        "mma.sync.aligned.m16n8k8.row.col.f32.tf32.tf32.f32 "
        "{%0,%1,%2,%3}, {%4,%5,%6,%7}, {%8,%9}, {%0,%1,%2,%3};"
        : "+f"(d[0]), "+f"(d[1]), "+f"(d[2]), "+f"(d[3])
        : "r"(a[0]), "r"(a[1]), "r"(a[2]), "r"(a[3]), "r"(b[0]), "r"(b[1]));
}

// ---------------------------------------------------------------------------
// tf32 rounding copy (also used in-place): n4 = element count / 4
// ---------------------------------------------------------------------------
__global__ void round_tf32(const float* __restrict__ in, float* __restrict__ out, int n4)
{
    int i = blockIdx.x * blockDim.x + threadIdx.x;
    if (i < n4) {
        float4 v = ((const float4*)in)[i];
        v.x = tf32r(v.x); v.y = tf32r(v.y); v.z = tf32r(v.z); v.w = tf32r(v.w);
        ((float4*)out)[i] = v;
    }
}

// ---------------------------------------------------------------------------
// tf32 mma.sync GEMM: C[M,N] = A[M,K] @ B[K,N] (+bias)
// 128x128x32 CTA tile, 256 threads (8 warps, warp tile 32x64), cp.async
// 2-stage pipeline. A/B pre-rounded to tf32.
// smem: A[2][128][36], B[2][32][136]  (71680 B dynamic)
// ---------------------------------------------------------------------------
#define GA_PITCH 36
#define GB_PITCH 136
#define GA_STG_F (128 * GA_PITCH)        // floats per A stage (4608)
#define GB_STG_F (32 * GB_PITCH)         // floats per B stage (4352)
#define GEMM_SMEM ((2 * GA_STG_F + 2 * GB_STG_F) * 4)

__global__ __launch_bounds__(256) void mma_gemm(
    const float* __restrict__ A, const float* __restrict__ B,
    float* __restrict__ C, int N, int K, const float* __restrict__ bias)
{
    extern __shared__ float smem[];
    float* sAf = smem;                       // 2 A stages
    float* sBf = smem + 2 * GA_STG_F;        // 2 B stages
    const uint32_t sbase = smem_u32(smem);

    const int t    = threadIdx.x;
    const int wid  = t >> 5, lane = t & 31;
    const int g    = lane >> 2, tg = lane & 3;
    const int wm   = wid >> 1, wn = wid & 1;
    const int bm   = blockIdx.y * 128;
    const int bn   = blockIdx.x * 128;

    const float* Ag = A + (size_t)bm * K;
    const float* Bg = B + bn;

    // per-thread staging coords
    const int arow = t >> 1,  acol = (t & 1) * 16;     // A: 2 thr/row, 4xf4 each
    const int brow = t >> 3,  bcol = (t & 7) * 4;      // B: 8 thr/row, 4xf4 each (stride 32)

    const int nk = K / 32;

    // stage loader
    auto loadStage = [&](int s, int kt) {
        uint32_t ad = sbase + (uint32_t)(s * GA_STG_F + arow * GA_PITCH + acol) * 4u;
        const float* as = Ag + (size_t)arow * K + kt * 32 + acol;
#pragma unroll
        for (int u = 0; u < 4; u++) cp16(ad + u * 16, as + u * 4);
        uint32_t bd = sbase + (uint32_t)((2 * GA_STG_F) + s * GB_STG_F + brow * GB_PITCH + bcol) * 4u;
        const float* bs = Bg + (size_t)(kt * 32 + brow) * N + bcol;
#pragma unroll
        for (int u = 0; u < 4; u++) cp16(bd + u * 128, bs + u * 32);
    };

    float acc[2][8][4];
#pragma unroll
    for (int i = 0; i < 2; i++)
#pragma unroll
        for (int j = 0; j < 8; j++)
#pragma unroll
            for (int c = 0; c < 4; c++) acc[i][j][c] = 0.f;

    loadStage(0, 0);
    cp_commit();

    for (int kt = 0; kt < nk; kt++) {
        if (kt + 1 < nk) {
            loadStage((kt + 1) & 1, kt + 1);
            cp_commit();
            cp_wait1();
        } else {
            cp_wait0();
        }
        __syncthreads();

        const float* sa = sAf + (kt & 1) * GA_STG_F;
        const float* sb = sBf + (kt & 1) * GB_STG_F;

#pragma unroll
        for (int ks = 0; ks < 4; ks++) {
            uint32_t a[2][4];
#pragma unroll
            for (int i = 0; i < 2; i++) {
                const int row = wm * 32 + i * 16 + g;
                a[i][0] = __float_as_uint(sa[(row    ) * GA_PITCH + ks * 8 + tg    ]);
                a[i][1] = __float_as_uint(sa[(row + 8) * GA_PITCH + ks * 8 + tg    ]);
                a[i][2] = __float_as_uint(sa[(row    ) * GA_PITCH + ks * 8 + tg + 4]);
                a[i][3] = __float_as_uint(sa[(row + 8) * GA_PITCH + ks * 8 + tg + 4]);
            }
            uint32_t b[8][2];
#pragma unroll
            for (int j = 0; j < 8; j++) {
                const int col = wn * 64 + j * 8 + g;
                b[j][0] = __float_as_uint(sb[(ks * 8 + tg    ) * GB_PITCH + col]);
                b[j][1] = __float_as_uint(sb[(ks * 8 + tg + 4) * GB_PITCH + col]);
            }
#pragma unroll
            for (int i = 0; i < 2; i++)
#pragma unroll
                for (int j = 0; j < 8; j++)
                    mma_tf32(acc[i][j], a[i], b[j]);
        }
        __syncthreads();
    }

    // Epilogue: c0/c1 at (row, 2tg..2tg+1), c2/c3 at (row+8). float2 stores
    // from 4 lanes cover full 32B sectors.
#pragma unroll
    for (int i = 0; i < 2; i++) {
        const int row = bm + wm * 32 + i * 16 + g;
#pragma unroll
        for (int j = 0; j < 8; j++) {
            const int col = bn + wn * 64 + j * 8 + tg * 2;
            float2 v0 = make_float2(acc[i][j][0], acc[i][j][1]);
            float2 v1 = make_float2(acc[i][j][2], acc[i][j][3]);
            if (bias) {
                float b0 = bias[col], b1 = bias[col + 1];
                v0.x += b0; v0.y += b1;
                v1.x += b0; v1.y += b1;
            }
            *(float2*)(C + (size_t)row * N + col)       = v0;
            *(float2*)(C + (size_t)(row + 8) * N + col) = v1;
        }
    }
}

// ---------------------------------------------------------------------------
// L2-normalize per (b,s,h) head-row of 64. One warp per row, 2 elems/lane.
// ---------------------------------------------------------------------------
__global__ void normalize_kernel(float* __restrict__ q, float* __restrict__ kv,
                                 const float* __restrict__ scale)
{
    const int warp  = (blockIdx.x * blockDim.x + threadIdx.x) >> 5;
    const int lane  = threadIdx.x & 31;
    const int total = MROWS * HH;
    const bool isQ  = warp < total;
    const int  r    = isQ ? warp : warp - total;
    if (r >= total) return;
    const int bs = r >> 4;
    const int h  = r & 15;

    float* ptr = isQ ? (q  + (size_t)bs * DD       + h * DHD)
                     : (kv + (size_t)bs * (2 * DD) + h * DHD);

    float2 v = *(float2*)(ptr + lane * 2);
    float ss = v.x * v.x + v.y * v.y;
#pragma unroll
    for (int m = 16; m > 0; m >>= 1) ss += __shfl_xor_sync(0xffffffffu, ss, m);

    float nrm = sqrtf(ss);
    float f   = 1.f / fmaxf(nrm, 1e-12f);
    if (isQ) f *= expf(scale[h]);
    v.x *= f;
    v.y *= f;
    *(float2*)(ptr + lane * 2) = v;
}

// ---------------------------------------------------------------------------
// Flash attention fp32 (validated in R1): 64x64 Q-tile, 256 threads, max-free
// softmax (|logit| <= exp(scale) ~ 0.0455).
// ---------------------------------------------------------------------------
#define FLASH_SMEM (4 * 64 * 68 * 4)

__global__ __launch_bounds__(256) void flash_kernel(
    const float* __restrict__ q, const float* __restrict__ kv, float* __restrict__ o)
{
    extern __shared__ float fsm[];
    float (*Qt)[68] = (float (*)[68])(fsm);
    float (*Kt)[68] = (float (*)[68])(fsm + 64 * 68);
    float (*Vs)[68] = (float (*)[68])(fsm + 2 * 64 * 68);
    float (*Ps)[68] = (float (*)[68])(fsm + 3 * 64 * 68);

    const int qt = blockIdx.x;
    const int h  = blockIdx.y;
    const int b  = blockIdx.z;
    const int tid = threadIdx.x;
    const int tx = tid & 15, ty = tid >> 4;

    const float* qbase = q  + ((size_t)(b * SS) + qt * 64) * DD + h * DHD;
    const float* kbase = kv + (size_t)(b * SS) * (2 * DD) + h * DHD;
    const float* vbase = kbase + DD;

    {
        const int r  = tid >> 2;
        const int c0 = (tid & 3) * 16;
#pragma unroll
        for (int u = 0; u < 4; u++) {
            float4 qv = *(const float4*)(qbase + (size_t)r * DD + c0 + u * 4);
            Qt[c0 + u * 4 + 0][r] = qv.x;
            Qt[c0 + u * 4 + 1][r] = qv.y;
            Qt[c0 + u * 4 + 2][r] = qv.z;
            Qt[c0 + u * 4 + 3][r] = qv.w;
        }
    }

    float l[4];
    float oacc[4][4];
#pragma unroll
    for (int i = 0; i < 4; i++) {
        l[i] = 0.f;
#pragma unroll
        for (int c = 0; c < 4; c++) oacc[i][c] = 0.f;
    }

    for (int jt = 0; jt < SS / 64; jt++) {
        __syncthreads();
        {
            const int r  = tid >> 2;
            const int c0 = (tid & 3) * 16;
            const float* krow = kbase + (size_t)(jt * 64 + r) * (2 * DD);
            const float* vrow = vbase + (size_t)(jt * 64 + r) * (2 * DD);
#pragma unroll
            for (int u = 0; u < 4; u++) {
                float4 kk = *(const float4*)(krow + c0 + u * 4);
                Kt[c0 + u * 4 + 0][r] = kk.x;
                Kt[c0 + u * 4 + 1][r] = kk.y;
                Kt[c0 + u * 4 + 2][r] = kk.z;
                Kt[c0 + u * 4 + 3][r] = kk.w;
                *(float4*)&Vs[r][c0 + u * 4] = *(const float4*)(vrow + c0 + u * 4);
            }
        }
        __syncthreads();

        float s[4][4];
#pragma unroll
        for (int i = 0; i < 4; i++)
#pragma unroll
            for (int j = 0; j < 4; j++) s[i][j] = 0.f;

#pragma unroll 8
        for (int d = 0; d < 64; d++) {
            float ra[4], rb[4];
            *(float4*)ra = *(float4*)&Qt[d][ty * 4];
            *(float4*)rb = *(float4*)&Kt[d][tx * 4];
#pragma unroll
            for (int i = 0; i < 4; i++)
#pragma unroll
                for (int j = 0; j < 4; j++)
                    s[i][j] += ra[i] * rb[j];
        }

#pragma unroll
        for (int i = 0; i < 4; i++) {
            float sum = 0.f;
#pragma unroll
            for (int j = 0; j < 4; j++) {
                float p = expf(s[i][j]);
                Ps[ty * 4 + i][tx * 4 + j] = p;
                sum += p;
            }
#pragma unroll
            for (int mk = 1; mk < 16; mk <<= 1)
                sum += __shfl_xor_sync(0xffffffffu, sum, mk);
            l[i] += sum;
        }
        __syncthreads();

#pragma unroll 8
        for (int j = 0; j < 64; j++) {
            float pa[4], vb[4];
#pragma unroll
            for (int i = 0; i < 4; i++) pa[i] = Ps[ty * 4 + i][j];
            *(float4*)vb = *(float4*)&Vs[j][tx * 4];
#pragma unroll
            for (int i = 0; i < 4; i++)
#pragma unroll
                for (int c = 0; c < 4; c++)
                    oacc[i][c] += pa[i] * vb[c];
        }
    }

    float* obase = o + ((size_t)(b * SS) + qt * 64) * DD + h * DHD;
#pragma unroll
    for (int i = 0; i < 4; i++) {
        float inv = 1.f / l[i];
        float4 v;
        v.x = oacc[i][0] * inv;
        v.y = oacc[i][1] * inv;
        v.z = oacc[i][2] * inv;
        v.w = oacc[i][3] * inv;
        *(float4*)(obase + (size_t)(ty * 4 + i) * DD + tx * 4) = v;
    }
}

// ---------------------------------------------------------------------------
extern "C" void kernel_launch(void* const* d_in, const int* in_sizes, int n_in,
                              void* d_out, int out_size)
{
    const float* x     = (const float*)d_in[0];
    const float* w_q   = (const float*)d_in[1];
    const float* w_kv  = (const float*)d_in[2];
    const float* w_out = (const float*)d_in[3];
    const float* b_out = (const float*)d_in[4];
    const float* scale = (const float*)d_in[5];
    float* out = (float*)d_out;

    float *px, *pq, *pkv, *po, *pwq, *pwkv, *pwo;
    cudaGetSymbolAddress((void**)&px,   g_x);
    cudaGetSymbolAddress((void**)&pq,   g_q);
    cudaGetSymbolAddress((void**)&pkv,  g_kv);
    cudaGetSymbolAddress((void**)&po,   g_o);
    cudaGetSymbolAddress((void**)&pwq,  g_wq);
    cudaGetSymbolAddress((void**)&pwkv, g_wkv);
    cudaGetSymbolAddress((void**)&pwo,  g_wo);

    cudaFuncSetAttribute(flash_kernel, cudaFuncAttributeMaxDynamicSharedMemorySize, FLASH_SMEM);
    cudaFuncSetAttribute(mma_gemm, cudaFuncAttributeMaxDynamicSharedMemorySize, GEMM_SMEM);

    // tf32-round all GEMM operands (unbiased rna rounding keeps rel_err ~1e-4)
    const int T = 256;
    round_tf32<<<(MROWS * DD / 4 + T - 1) / T, T>>>(x, px, MROWS * DD / 4);
    round_tf32<<<(DD * DD / 4 + T - 1) / T, T>>>(w_q, pwq, DD * DD / 4);
    round_tf32<<<(2 * DD * DD / 4 + T - 1) / T, T>>>(w_kv, pwkv, 2 * DD * DD / 4);
    round_tf32<<<(DD * DD / 4 + T - 1) / T, T>>>(w_out, pwo, DD * DD / 4);

    // q = x @ w_q ; kv = x @ w_kv
    mma_gemm<<<dim3(DD / 128, MROWS / 128), 256, GEMM_SMEM>>>(px, pwq, pq, DD, DD, nullptr);
    mma_gemm<<<dim3(2 * DD / 128, MROWS / 128), 256, GEMM_SMEM>>>(px, pwkv, pkv, 2 * DD, DD, nullptr);

    // L2-normalize q (x exp(scale)) and k
    normalize_kernel<<<(2 * MROWS * HH) / 8, 256>>>(pq, pkv, scale);

    // attention
    flash_kernel<<<dim3(SS / 64, HH, BB), 256, FLASH_SMEM>>>(pq, pkv, po);

    // round attention output for final tf32 GEMM, then out = g_o @ w_out + b_out
    round_tf32<<<(MROWS * DD / 4 + T - 1) / T, T>>>(po, po, MROWS * DD / 4);
    mma_gemm<<<dim3(DD / 128, MROWS / 128), 256, GEMM_SMEM>>>(po, pwo, out, DD, DD, b_out);
}

// round 5
// speedup vs baseline: 2.6212x; 1.8908x over previous
#include <cuda_runtime.h>
#include <math.h>
#include <stdint.h>

// Problem constants: B=2, S=2048, D=1024, H=16, DH=64, INNER=1024
#define BB   2
#define SS   2048
#define DD   1024
#define HH   16
#define DHD  64
#define MROWS (BB * SS)   // 4096 token rows

// Scratch (static device globals -- no allocations allowed)
__device__ float g_x  [(size_t)MROWS * DD];         // tf32-rounded x
__device__ float g_q  [(size_t)MROWS * DD];         // q projection (normalized in place)
__device__ float g_kv [(size_t)MROWS * 2 * DD];     // [k | v] projection
__device__ float g_o  [(size_t)MROWS * DD];         // attention output before w_out
__device__ float g_wq [(size_t)DD * DD];            // tf32-rounded w_q
__device__ float g_wkv[(size_t)DD * 2 * DD];        // tf32-rounded w_kv
__device__ float g_wo [(size_t)DD * DD];            // tf32-rounded w_out

// ---------------------------------------------------------------------------
// helpers
// ---------------------------------------------------------------------------
__device__ __forceinline__ uint32_t smem_u32(const void* p) {
    uint32_t a;
    asm("{ .reg .u64 t; cvta.to.shared.u64 t, %1; cvt.u32.u64 %0, t; }" : "=r"(a) : "l"(p));
    return a;
}

__device__ __forceinline__ float tf32r(float x) {
    uint32_t u;
    asm("cvt.rna.tf32.f32 %0, %1;" : "=r"(u) : "f"(x));
    return __uint_as_float(u);
}

__device__ __forceinline__ void cp16(uint32_t dst, const void* src) {
    asm volatile("cp.async.cg.shared.global [%0], [%1], 16;" :: "r"(dst), "l"(src));
}
__device__ __forceinline__ void cp_commit() {
    asm volatile("cp.async.commit_group;" ::: "memory");
}
__device__ __forceinline__ void cp_wait1() {
    asm volatile("cp.async.wait_group 1;" ::: "memory");
}
__device__ __forceinline__ void cp_wait0() {
    asm volatile("cp.async.wait_group 0;" ::: "memory");
}

__device__ __forceinline__ void mma_tf32(float* d, const uint32_t* a, const uint32_t* b) {
    asm volatile(
        "mma.sync.aligned.m16n8k8.row.col.f32.tf32.tf32.f32 "
        "{%0,%1,%2,%3}, {%4,%5,%6,%7}, {%8,%9}, {%0,%1,%2,%3};"
        : "+f"(d[0]), "+f"(d[1]), "+f"(d[2]), "+f"(d[3])
        : "r"(a[0]), "r"(a[1]), "r"(a[2]), "r"(a[3]), "r"(b[0]), "r"(b[1]));
}

// ---------------------------------------------------------------------------
// tf32 rounding copy (also used in-place): n4 = element count / 4
// ---------------------------------------------------------------------------
__global__ void round_tf32(const float* __restrict__ in, float* __restrict__ out, int n4)
{
    int i = blockIdx.x * blockDim.x + threadIdx.x;
    if (i < n4) {
        float4 v = ((const float4*)in)[i];
        v.x = tf32r(v.x); v.y = tf32r(v.y); v.z = tf32r(v.z); v.w = tf32r(v.w);
        ((float4*)out)[i] = v;
    }
}

// ---------------------------------------------------------------------------
// tf32 mma.sync GEMM: C[M,N] = A[M,K] @ B[K,N] (+bias)   (validated R3)
// 128x128x32 CTA tile, 256 threads (8 warps, warp tile 32x64), cp.async
// 2-stage pipeline. smem: A[2][128][36], B[2][32][136]
// ---------------------------------------------------------------------------
#define GA_PITCH 36
#define GB_PITCH 136
#define GA_STG_F (128 * GA_PITCH)
#define GB_STG_F (32 * GB_PITCH)
#define GEMM_SMEM ((2 * GA_STG_F + 2 * GB_STG_F) * 4)

__global__ __launch_bounds__(256) void mma_gemm(
    const float* __restrict__ A, const float* __restrict__ B,
    float* __restrict__ C, int N, int K, const float* __restrict__ bias)
{
    extern __shared__ float smem[];
    float* sAf = smem;
    float* sBf = smem + 2 * GA_STG_F;
    const uint32_t sbase = smem_u32(smem);

    const int t    = threadIdx.x;
    const int wid  = t >> 5, lane = t & 31;
    const int g    = lane >> 2, tg = lane & 3;
    const int wm   = wid >> 1, wn = wid & 1;
    const int bm   = blockIdx.y * 128;
    const int bn   = blockIdx.x * 128;

    const float* Ag = A + (size_t)bm * K;
    const float* Bg = B + bn;

    const int arow = t >> 1,  acol = (t & 1) * 16;
    const int brow = t >> 3,  bcol = (t & 7) * 4;

    const int nk = K / 32;

    auto loadStage = [&](int s, int kt) {
        uint32_t ad = sbase + (uint32_t)(s * GA_STG_F + arow * GA_PITCH + acol) * 4u;
        const float* as = Ag + (size_t)arow * K + kt * 32 + acol;
#pragma unroll
        for (int u = 0; u < 4; u++) cp16(ad + u * 16, as + u * 4);
        uint32_t bd = sbase + (uint32_t)((2 * GA_STG_F) + s * GB_STG_F + brow * GB_PITCH + bcol) * 4u;
        const float* bs = Bg + (size_t)(kt * 32 + brow) * N + bcol;
#pragma unroll
        for (int u = 0; u < 4; u++) cp16(bd + u * 128, bs + u * 32);
    };

    float acc[2][8][4];
#pragma unroll
    for (int i = 0; i < 2; i++)
#pragma unroll
        for (int j = 0; j < 8; j++)
#pragma unroll
            for (int c = 0; c < 4; c++) acc[i][j][c] = 0.f;

    loadStage(0, 0);
    cp_commit();

    for (int kt = 0; kt < nk; kt++) {
        if (kt + 1 < nk) {
            loadStage((kt + 1) & 1, kt + 1);
            cp_commit();
            cp_wait1();
        } else {
            cp_wait0();
        }
        __syncthreads();

        const float* sa = sAf + (kt & 1) * GA_STG_F;
        const float* sb = sBf + (kt & 1) * GB_STG_F;

#pragma unroll
        for (int ks = 0; ks < 4; ks++) {
            uint32_t a[2][4];
#pragma unroll
            for (int i = 0; i < 2; i++) {
                const int row = wm * 32 + i * 16 + g;
                a[i][0] = __float_as_uint(sa[(row    ) * GA_PITCH + ks * 8 + tg    ]);
                a[i][1] = __float_as_uint(sa[(row + 8) * GA_PITCH + ks * 8 + tg    ]);
                a[i][2] = __float_as_uint(sa[(row    ) * GA_PITCH + ks * 8 + tg + 4]);
                a[i][3] = __float_as_uint(sa[(row + 8) * GA_PITCH + ks * 8 + tg + 4]);
            }
            uint32_t b[8][2];
#pragma unroll
            for (int j = 0; j < 8; j++) {
                const int col = wn * 64 + j * 8 + g;
                b[j][0] = __float_as_uint(sb[(ks * 8 + tg    ) * GB_PITCH + col]);
                b[j][1] = __float_as_uint(sb[(ks * 8 + tg + 4) * GB_PITCH + col]);
            }
#pragma unroll
            for (int i = 0; i < 2; i++)
#pragma unroll
                for (int j = 0; j < 8; j++)
                    mma_tf32(acc[i][j], a[i], b[j]);
        }
        __syncthreads();
    }

#pragma unroll
    for (int i = 0; i < 2; i++) {
        const int row = bm + wm * 32 + i * 16 + g;
#pragma unroll
        for (int j = 0; j < 8; j++) {
            const int col = bn + wn * 64 + j * 8 + tg * 2;
            float2 v0 = make_float2(acc[i][j][0], acc[i][j][1]);
            float2 v1 = make_float2(acc[i][j][2], acc[i][j][3]);
            if (bias) {
                float b0 = bias[col], b1 = bias[col + 1];
                v0.x += b0; v0.y += b1;
                v1.x += b0; v1.y += b1;
            }
            *(float2*)(C + (size_t)row * N + col)       = v0;
            *(float2*)(C + (size_t)(row + 8) * N + col) = v1;
        }
    }
}

// ---------------------------------------------------------------------------
// L2-normalize q (x exp(scale)) and k per head-row; round q,k AND v to tf32
// so all flash mma operands are unbiased-rounded. One warp per head-row.
// Segments: [0,T) = q rows, [T,2T) = k rows, [2T,3T) = v rows (round only).
// ---------------------------------------------------------------------------
__global__ void normalize_kernel(float* __restrict__ q, float* __restrict__ kv,
                                 const float* __restrict__ scale)
{
    const int warp  = (blockIdx.x * blockDim.x + threadIdx.x) >> 5;
    const int lane  = threadIdx.x & 31;
    const int total = MROWS * HH;
    if (warp >= 3 * total) return;
    const int seg = warp / total;          // 0=q, 1=k, 2=v
    const int r   = warp - seg * total;
    const int bs  = r >> 4;
    const int h   = r & 15;

    float* ptr;
    if (seg == 0)      ptr = q  + (size_t)bs * DD       + h * DHD;
    else if (seg == 1) ptr = kv + (size_t)bs * (2 * DD) + h * DHD;
    else               ptr = kv + (size_t)bs * (2 * DD) + DD + h * DHD;

    float2 v = *(float2*)(ptr + lane * 2);

    if (seg < 2) {
        float ss = v.x * v.x + v.y * v.y;
#pragma unroll
        for (int m = 16; m > 0; m >>= 1) ss += __shfl_xor_sync(0xffffffffu, ss, m);
        float f = 1.f / fmaxf(sqrtf(ss), 1e-12f);
        if (seg == 0) f *= expf(scale[h]);
        v.x *= f;
        v.y *= f;
    }
    v.x = tf32r(v.x);
    v.y = tf32r(v.y);
    *(float2*)(ptr + lane * 2) = v;
}

// ---------------------------------------------------------------------------
// Flash attention, tf32 mma.sync for QK^T and PV.
// CTA: 128 q-rows, 8 warps (16 rows each), 64-key tiles, 32 iterations.
// Max-free softmax (|logit| <= exp(scale) ~ 0.0455) with __expf.
// Smem: Qs[128][68], Kt[64][72] ([dh][key]), Vs[64][72] ([key][dh]), Ps[128][68]
// ---------------------------------------------------------------------------
#define FQ 128
#define FKT 64
#define QP 68
#define KP 72
#define VP 72
#define PP 68
#define FLASH_SMEM ((FQ * QP + FKT * KP + FKT * VP + FQ * PP) * 4)   // 106496 B

__global__ __launch_bounds__(256) void flash_mma(
    const float* __restrict__ q, const float* __restrict__ kv, float* __restrict__ o)
{
    extern __shared__ float sm[];
    float* Qs = sm;                      // [128][68]
    float* Kt = Qs + FQ * QP;            // [64][72]  (dh, key)
    float* Vs = Kt + FKT * KP;           // [64][72]  (key, dh)
    float* Ps = Vs + FKT * VP;           // [128][68]

    const int qt = blockIdx.x, h = blockIdx.y, b = blockIdx.z;
    const int tid = threadIdx.x, wid = tid >> 5, lane = tid & 31;
    const int g = lane >> 2, tg = lane & 3;
    const int m0 = wid * 16;

    const float* qbase = q  + ((size_t)(b * SS) + qt * FQ) * DD + h * DHD;
    const float* kbase = kv + (size_t)(b * SS) * (2 * DD) + h * DHD;
    const float* vbase = kbase + DD;

    // Load Q tile (already tf32-rounded): 128 rows x 64 cols, 2 threads/row
    {
        const int r = tid >> 1, c0 = (tid & 1) * 32;
#pragma unroll
        for (int u = 0; u < 8; u++) {
            float4 v = *(const float4*)(qbase + (size_t)r * DD + c0 + u * 4);
            *(float4*)&Qs[r * QP + c0 + u * 4] = v;
        }
    }

    float l0 = 0.f, l1 = 0.f;
    float oacc[8][4];
#pragma unroll
    for (int j = 0; j < 8; j++)
#pragma unroll
        for (int c = 0; c < 4; c++) oacc[j][c] = 0.f;

    for (int jt = 0; jt < SS / FKT; jt++) {
        __syncthreads();   // protect Kt/Vs vs previous iteration's GEMM2 readers
        {
            const int r = tid >> 2, c0 = (tid & 3) * 16;
            const float* krow = kbase + (size_t)(jt * FKT + r) * (2 * DD);
            const float* vrow = vbase + (size_t)(jt * FKT + r) * (2 * DD);
#pragma unroll
            for (int u = 0; u < 4; u++) {
                float4 kk = *(const float4*)(krow + c0 + u * 4);
                Kt[(c0 + u * 4 + 0) * KP + r] = kk.x;
                Kt[(c0 + u * 4 + 1) * KP + r] = kk.y;
                Kt[(c0 + u * 4 + 2) * KP + r] = kk.z;
                Kt[(c0 + u * 4 + 3) * KP + r] = kk.w;
                *(float4*)&Vs[r * VP + c0 + u * 4] = *(const float4*)(vrow + c0 + u * 4);
            }
        }
        __syncthreads();

        // GEMM1: S[16x64] = Q[16x64] @ K^T
        float sacc[8][4];
#pragma unroll
        for (int j = 0; j < 8; j++)
#pragma unroll
            for (int c = 0; c < 4; c++) sacc[j][c] = 0.f;

#pragma unroll
        for (int ks = 0; ks < 8; ks++) {
            uint32_t a[4];
            a[0] = __float_as_uint(Qs[(m0 + g    ) * QP + ks * 8 + tg    ]);
            a[1] = __float_as_uint(Qs[(m0 + g + 8) * QP + ks * 8 + tg    ]);
            a[2] = __float_as_uint(Qs[(m0 + g    ) * QP + ks * 8 + tg + 4]);
            a[3] = __float_as_uint(Qs[(m0 + g + 8) * QP + ks * 8 + tg + 4]);
#pragma unroll
            for (int j = 0; j < 8; j++) {
                uint32_t bb[2];
                bb[0] = __float_as_uint(Kt[(ks * 8 + tg    ) * KP + j * 8 + g]);
                bb[1] = __float_as_uint(Kt[(ks * 8 + tg + 4) * KP + j * 8 + g]);
                mma_tf32(sacc[j], a, bb);
            }
        }

        // Softmax numerator (max-free), tf32-round P, accumulate row sums
        float rs0 = 0.f, rs1 = 0.f;
#pragma unroll
        for (int j = 0; j < 8; j++) {
            float p0 = tf32r(__expf(sacc[j][0]));
            float p1 = tf32r(__expf(sacc[j][1]));
            float p2 = tf32r(__expf(sacc[j][2]));
            float p3 = tf32r(__expf(sacc[j][3]));
            rs0 += p0 + p1;
            rs1 += p2 + p3;
            *(float2*)&Ps[(m0 + g    ) * PP + j * 8 + 2 * tg] = make_float2(p0, p1);
            *(float2*)&Ps[(m0 + g + 8) * PP + j * 8 + 2 * tg] = make_float2(p2, p3);
        }
        rs0 += __shfl_xor_sync(0xffffffffu, rs0, 1);
        rs0 += __shfl_xor_sync(0xffffffffu, rs0, 2);
        rs1 += __shfl_xor_sync(0xffffffffu, rs1, 1);
        rs1 += __shfl_xor_sync(0xffffffffu, rs1, 2);
        l0 += rs0;
        l1 += rs1;
        __syncwarp();   // Ps rows are warp-local: warp fence suffices

        // GEMM2: O[16x64] += P[16x64] @ V[64x64]
#pragma unroll
        for (int ks = 0; ks < 8; ks++) {
            uint32_t a[4];
            a[0] = __float_as_uint(Ps[(m0 + g    ) * PP + ks * 8 + tg    ]);
            a[1] = __float_as_uint(Ps[(m0 + g + 8) * PP + ks * 8 + tg    ]);
            a[2] = __float_as_uint(Ps[(m0 + g    ) * PP + ks * 8 + tg + 4]);
            a[3] = __float_as_uint(Ps[(m0 + g + 8) * PP + ks * 8 + tg + 4]);
#pragma unroll
            for (int j = 0; j < 8; j++) {
                uint32_t bb[2];
                bb[0] = __float_as_uint(Vs[(ks * 8 + tg    ) * VP + j * 8 + g]);
                bb[1] = __float_as_uint(Vs[(ks * 8 + tg + 4) * VP + j * 8 + g]);
                mma_tf32(oacc[j], a, bb);
            }
        }
        __syncwarp();   // keep Ps reads inside this iteration
    }

    // Epilogue: divide by softmax denominator, store
    float* obase = o + ((size_t)(b * SS) + qt * FQ) * DD + h * DHD;
    const float inv0 = 1.f / l0, inv1 = 1.f / l1;
#pragma unroll
    for (int j = 0; j < 8; j++) {
        const int col = j * 8 + 2 * tg;
        *(float2*)(obase + (size_t)(m0 + g    ) * DD + col) =
            make_float2(oacc[j][0] * inv0, oacc[j][1] * inv0);
        *(float2*)(obase + (size_t)(m0 + g + 8) * DD + col) =
            make_float2(oacc[j][2] * inv1, oacc[j][3] * inv1);
    }
}

// ---------------------------------------------------------------------------
extern "C" void kernel_launch(void* const* d_in, const int* in_sizes, int n_in,
                              void* d_out, int out_size)
{
    const float* x     = (const float*)d_in[0];
    const float* w_q   = (const float*)d_in[1];
    const float* w_kv  = (const float*)d_in[2];
    const float* w_out = (const float*)d_in[3];
    const float* b_out = (const float*)d_in[4];
    const float* scale = (const float*)d_in[5];
    float* out = (float*)d_out;

    float *px, *pq, *pkv, *po, *pwq, *pwkv, *pwo;
    cudaGetSymbolAddress((void**)&px,   g_x);
    cudaGetSymbolAddress((void**)&pq,   g_q);
    cudaGetSymbolAddress((void**)&pkv,  g_kv);
    cudaGetSymbolAddress((void**)&po,   g_o);
    cudaGetSymbolAddress((void**)&pwq,  g_wq);
    cudaGetSymbolAddress((void**)&pwkv, g_wkv);
    cudaGetSymbolAddress((void**)&pwo,  g_wo);

    cudaFuncSetAttribute(flash_mma, cudaFuncAttributeMaxDynamicSharedMemorySize, FLASH_SMEM);
    cudaFuncSetAttribute(mma_gemm, cudaFuncAttributeMaxDynamicSharedMemorySize, GEMM_SMEM);

    // tf32-round all GEMM operands (unbiased rna rounding)
    const int T = 256;
    round_tf32<<<(MROWS * DD / 4 + T - 1) / T, T>>>(x, px, MROWS * DD / 4);
    round_tf32<<<(DD * DD / 4 + T - 1) / T, T>>>(w_q, pwq, DD * DD / 4);
    round_tf32<<<(2 * DD * DD / 4 + T - 1) / T, T>>>(w_kv, pwkv, 2 * DD * DD / 4);
    round_tf32<<<(DD * DD / 4 + T - 1) / T, T>>>(w_out, pwo, DD * DD / 4);

    // q = x @ w_q ; kv = x @ w_kv
    mma_gemm<<<dim3(DD / 128, MROWS / 128), 256, GEMM_SMEM>>>(px, pwq, pq, DD, DD, nullptr);
    mma_gemm<<<dim3(2 * DD / 128, MROWS / 128), 256, GEMM_SMEM>>>(px, pwkv, pkv, 2 * DD, DD, nullptr);

    // L2-normalize q (x exp(scale)) and k; tf32-round q, k, v
    normalize_kernel<<<(3 * MROWS * HH) / 8, 256>>>(pq, pkv, scale);

    // attention (tensor-core flash)
    flash_mma<<<dim3(SS / FQ, HH, BB), 256, FLASH_SMEM>>>(pq, pkv, po);

    // round attention output, then out = g_o @ w_out + b_out
    round_tf32<<<(MROWS * DD / 4 + T - 1) / T, T>>>(po, po, MROWS * DD / 4);
    mma_gemm<<<dim3(DD / 128, MROWS / 128), 256, GEMM_SMEM>>>(po, pwo, out, DD, DD, b_out);
}

// round 6
// speedup vs baseline: 2.8157x; 1.0742x over previous
#include <cuda_runtime.h>
#include <math.h>
#include <stdint.h>

// Problem constants: B=2, S=2048, D=1024, H=16, DH=64, INNER=1024
#define BB   2
#define SS   2048
#define DD   1024
#define HH   16
#define DHD  64
#define MROWS (BB * SS)   // 4096 token rows

// Scratch (static device globals -- no allocations allowed)
__device__ float g_x  [(size_t)MROWS * DD];         // tf32-rounded x
__device__ float g_q  [(size_t)MROWS * DD];         // q projection (normalized in place)
__device__ float g_kv [(size_t)MROWS * 2 * DD];     // [k | v] projection
__device__ float g_o  [(size_t)MROWS * DD];         // attention output (tf32-rounded)
__device__ float g_wq [(size_t)DD * DD];            // tf32-rounded w_q
__device__ float g_wkv[(size_t)DD * 2 * DD];        // tf32-rounded w_kv
__device__ float g_wo [(size_t)DD * DD];            // tf32-rounded w_out

// ---------------------------------------------------------------------------
// helpers
// ---------------------------------------------------------------------------
__device__ __forceinline__ uint32_t smem_u32(const void* p) {
    uint32_t a;
    asm("{ .reg .u64 t; cvta.to.shared.u64 t, %1; cvt.u32.u64 %0, t; }" : "=r"(a) : "l"(p));
    return a;
}

__device__ __forceinline__ float tf32r(float x) {
    uint32_t u;
    asm("cvt.rna.tf32.f32 %0, %1;" : "=r"(u) : "f"(x));
    return __uint_as_float(u);
}

__device__ __forceinline__ void cp16(uint32_t dst, const void* src) {
    asm volatile("cp.async.cg.shared.global [%0], [%1], 16;" :: "r"(dst), "l"(src));
}
__device__ __forceinline__ void cp_commit() {
    asm volatile("cp.async.commit_group;" ::: "memory");
}
__device__ __forceinline__ void cp_wait1() {
    asm volatile("cp.async.wait_group 1;" ::: "memory");
}
__device__ __forceinline__ void cp_wait0() {
    asm volatile("cp.async.wait_group 0;" ::: "memory");
}

__device__ __forceinline__ void mma_tf32(float* d, const uint32_t* a, const uint32_t* b) {
    asm volatile(
        "mma.sync.aligned.m16n8k8.row.col.f32.tf32.tf32.f32 "
        "{%0,%1,%2,%3}, {%4,%5,%6,%7}, {%8,%9}, {%0,%1,%2,%3};"
        : "+f"(d[0]), "+f"(d[1]), "+f"(d[2]), "+f"(d[3])
        : "r"(a[0]), "r"(a[1]), "r"(a[2]), "r"(a[3]), "r"(b[0]), "r"(b[1]));
}

// ---------------------------------------------------------------------------
// tf32 rounding copy: n4 = element count / 4
// ---------------------------------------------------------------------------
__global__ void round_tf32(const float* __restrict__ in, float* __restrict__ out, int n4)
{
    int i = blockIdx.x * blockDim.x + threadIdx.x;
    if (i < n4) {
        float4 v = ((const float4*)in)[i];
        v.x = tf32r(v.x); v.y = tf32r(v.y); v.z = tf32r(v.z); v.w = tf32r(v.w);
        ((float4*)out)[i] = v;
    }
}

// ---------------------------------------------------------------------------
// tf32 mma.sync GEMM (validated R3): C[M,N] = A[M,K] @ B[K,N] (+bias)
// 128x128x32 CTA tile, 256 threads, cp.async 2-stage pipeline.
// ---------------------------------------------------------------------------
#define GA_PITCH 36
#define GB_PITCH 136
#define GA_STG_F (128 * GA_PITCH)
#define GB_STG_F (32 * GB_PITCH)
#define GEMM_SMEM ((2 * GA_STG_F + 2 * GB_STG_F) * 4)

__global__ __launch_bounds__(256) void mma_gemm(
    const float* __restrict__ A, const float* __restrict__ B,
    float* __restrict__ C, int N, int K, const float* __restrict__ bias)
{
    extern __shared__ float smem[];
    float* sAf = smem;
    float* sBf = smem + 2 * GA_STG_F;
    const uint32_t sbase = smem_u32(smem);

    const int t    = threadIdx.x;
    const int wid  = t >> 5, lane = t & 31;
    const int g    = lane >> 2, tg = lane & 3;
    const int wm   = wid >> 1, wn = wid & 1;
    const int bm   = blockIdx.y * 128;
    const int bn   = blockIdx.x * 128;

    const float* Ag = A + (size_t)bm * K;
    const float* Bg = B + bn;

    const int arow = t >> 1,  acol = (t & 1) * 16;
    const int brow = t >> 3,  bcol = (t & 7) * 4;

    const int nk = K / 32;

    auto loadStage = [&](int s, int kt) {
        uint32_t ad = sbase + (uint32_t)(s * GA_STG_F + arow * GA_PITCH + acol) * 4u;
        const float* as = Ag + (size_t)arow * K + kt * 32 + acol;
#pragma unroll
        for (int u = 0; u < 4; u++) cp16(ad + u * 16, as + u * 4);
        uint32_t bd = sbase + (uint32_t)((2 * GA_STG_F) + s * GB_STG_F + brow * GB_PITCH + bcol) * 4u;
        const float* bs = Bg + (size_t)(kt * 32 + brow) * N + bcol;
#pragma unroll
        for (int u = 0; u < 4; u++) cp16(bd + u * 128, bs + u * 32);
    };

    float acc[2][8][4];
#pragma unroll
    for (int i = 0; i < 2; i++)
#pragma unroll
        for (int j = 0; j < 8; j++)
#pragma unroll
            for (int c = 0; c < 4; c++) acc[i][j][c] = 0.f;

    loadStage(0, 0);
    cp_commit();

    for (int kt = 0; kt < nk; kt++) {
        if (kt + 1 < nk) {
            loadStage((kt + 1) & 1, kt + 1);
            cp_commit();
            cp_wait1();
        } else {
            cp_wait0();
        }
        __syncthreads();

        const float* sa = sAf + (kt & 1) * GA_STG_F;
        const float* sb = sBf + (kt & 1) * GB_STG_F;

#pragma unroll
        for (int ks = 0; ks < 4; ks++) {
            uint32_t a[2][4];
#pragma unroll
            for (int i = 0; i < 2; i++) {
                const int row = wm * 32 + i * 16 + g;
                a[i][0] = __float_as_uint(sa[(row    ) * GA_PITCH + ks * 8 + tg    ]);
                a[i][1] = __float_as_uint(sa[(row + 8) * GA_PITCH + ks * 8 + tg    ]);
                a[i][2] = __float_as_uint(sa[(row    ) * GA_PITCH + ks * 8 + tg + 4]);
                a[i][3] = __float_as_uint(sa[(row + 8) * GA_PITCH + ks * 8 + tg + 4]);
            }
            uint32_t b[8][2];
#pragma unroll
            for (int j = 0; j < 8; j++) {
                const int col = wn * 64 + j * 8 + g;
                b[j][0] = __float_as_uint(sb[(ks * 8 + tg    ) * GB_PITCH + col]);
                b[j][1] = __float_as_uint(sb[(ks * 8 + tg + 4) * GB_PITCH + col]);
            }
#pragma unroll
            for (int i = 0; i < 2; i++)
#pragma unroll
                for (int j = 0; j < 8; j++)
                    mma_tf32(acc[i][j], a[i], b[j]);
        }
        __syncthreads();
    }

#pragma unroll
    for (int i = 0; i < 2; i++) {
        const int row = bm + wm * 32 + i * 16 + g;
#pragma unroll
        for (int j = 0; j < 8; j++) {
            const int col = bn + wn * 64 + j * 8 + tg * 2;
            float2 v0 = make_float2(acc[i][j][0], acc[i][j][1]);
            float2 v1 = make_float2(acc[i][j][2], acc[i][j][3]);
            if (bias) {
                float b0 = bias[col], b1 = bias[col + 1];
                v0.x += b0; v0.y += b1;
                v1.x += b0; v1.y += b1;
            }
            *(float2*)(C + (size_t)row * N + col)       = v0;
            *(float2*)(C + (size_t)(row + 8) * N + col) = v1;
        }
    }
}

// ---------------------------------------------------------------------------
// L2-normalize q (x exp(scale)) and k; tf32-round q, k, v. One warp per row.
// ---------------------------------------------------------------------------
__global__ void normalize_kernel(float* __restrict__ q, float* __restrict__ kv,
                                 const float* __restrict__ scale)
{
    const int warp  = (blockIdx.x * blockDim.x + threadIdx.x) >> 5;
    const int lane  = threadIdx.x & 31;
    const int total = MROWS * HH;
    if (warp >= 3 * total) return;
    const int seg = warp / total;          // 0=q, 1=k, 2=v
    const int r   = warp - seg * total;
    const int bs  = r >> 4;
    const int h   = r & 15;

    float* ptr;
    if (seg == 0)      ptr = q  + (size_t)bs * DD       + h * DHD;
    else if (seg == 1) ptr = kv + (size_t)bs * (2 * DD) + h * DHD;
    else               ptr = kv + (size_t)bs * (2 * DD) + DD + h * DHD;

    float2 v = *(float2*)(ptr + lane * 2);

    if (seg < 2) {
        float ss = v.x * v.x + v.y * v.y;
#pragma unroll
        for (int m = 16; m > 0; m >>= 1) ss += __shfl_xor_sync(0xffffffffu, ss, m);
        float f = 1.f / fmaxf(sqrtf(ss), 1e-12f);
        if (seg == 0) f *= expf(scale[h]);
        v.x *= f;
        v.y *= f;
    }
    v.x = tf32r(v.x);
    v.y = tf32r(v.y);
    *(float2*)(ptr + lane * 2) = v;
}

// ---------------------------------------------------------------------------
// Flash attention, tf32 mma.sync, cp.async 2-stage K/V pipeline, Q fragments
// register-resident, Ps reuses the Qs smem region.
// CTA: 128 q-rows, 8 warps x 16 rows, 64-key tiles, 32 iterations.
// Smem: QsPs[128][68], 2 x ( Ks[64][68] + Vs[64][72] )  = 106496 B.
// Bank math: Ks pitch 68 -> B-frag bank (4g+tg)%32, all-distinct; Vs pitch 72
// -> (8tg+g)%32 all-distinct.
// ---------------------------------------------------------------------------
#define FQ  128
#define FKT 64
#define QP  68
#define KSP 68
#define VSP 72
#define KV_STG (FKT * KSP + FKT * VSP)     // floats per stage (8960)
#define FLASH_SMEM ((FQ * QP + 2 * KV_STG) * 4)

__global__ __launch_bounds__(256) void flash_mma(
    const float* __restrict__ q, const float* __restrict__ kv, float* __restrict__ o)
{
    extern __shared__ float sm[];
    float* QsPs = sm;                          // [128][68] : Q during prologue, P after
    float* Stg  = sm + FQ * QP;                // 2 stages of (Ks + Vs)
    const uint32_t sbase = smem_u32(sm);
    const uint32_t stgBase = sbase + FQ * QP * 4u;

    const int qt = blockIdx.x, h = blockIdx.y, b = blockIdx.z;
    const int tid = threadIdx.x, wid = tid >> 5, lane = tid & 31;
    const int g = lane >> 2, tg = lane & 3;
    const int m0 = wid * 16;

    const float* qbase = q  + ((size_t)(b * SS) + qt * FQ) * DD + h * DHD;
    const float* kbase = kv + (size_t)(b * SS) * (2 * DD) + h * DHD;
    const float* vbase = kbase + DD;

    // cp.async staging coords: 4 threads/row, 16 floats (4 x cp16) each
    const int sr = tid >> 2, sc = (tid & 3) * 16;

    auto prefetchKV = [&](int s, int jt) {
        const float* krow = kbase + (size_t)(jt * FKT + sr) * (2 * DD) + sc;
        const float* vrow = vbase + (size_t)(jt * FKT + sr) * (2 * DD) + sc;
        uint32_t kd = stgBase + (uint32_t)(s * KV_STG + sr * KSP + sc) * 4u;
        uint32_t vd = stgBase + (uint32_t)(s * KV_STG + FKT * KSP + sr * VSP + sc) * 4u;
#pragma unroll
        for (int u = 0; u < 4; u++) {
            cp16(kd + u * 16, krow + u * 4);
            cp16(vd + u * 16, vrow + u * 4);
        }
    };

    // Kick off stage 0 before touching Q
    prefetchKV(0, 0);
    cp_commit();

    // Stage Q (128 x 64, 2 threads/row), then hoist fragments to registers
    {
        const int r = tid >> 1, c0 = (tid & 1) * 32;
#pragma unroll
        for (int u = 0; u < 8; u++) {
            float4 v = *(const float4*)(qbase + (size_t)r * DD + c0 + u * 4);
            *(float4*)&QsPs[r * QP + c0 + u * 4] = v;
        }
    }
    __syncthreads();

    uint32_t qa[8][4];
#pragma unroll
    for (int ks = 0; ks < 8; ks++) {
        qa[ks][0] = __float_as_uint(QsPs[(m0 + g    ) * QP + ks * 8 + tg    ]);
        qa[ks][1] = __float_as_uint(QsPs[(m0 + g + 8) * QP + ks * 8 + tg    ]);
        qa[ks][2] = __float_as_uint(QsPs[(m0 + g    ) * QP + ks * 8 + tg + 4]);
        qa[ks][3] = __float_as_uint(QsPs[(m0 + g + 8) * QP + ks * 8 + tg + 4]);
    }
    // Qs region becomes Ps from here; first Ps write happens after the
    // __syncthreads at the top of iteration 0, so all frags are safely loaded.

    float l0 = 0.f, l1 = 0.f;
    float oacc[8][4];
#pragma unroll
    for (int j = 0; j < 8; j++)
#pragma unroll
        for (int c = 0; c < 4; c++) oacc[j][c] = 0.f;

    const int NT = SS / FKT;
    for (int jt = 0; jt < NT; jt++) {
        if (jt + 1 < NT) {
            prefetchKV((jt + 1) & 1, jt + 1);
            cp_commit();
            cp_wait1();
        } else {
            cp_wait0();
        }
        __syncthreads();   // staged K/V visible; also fences previous Ps usage

        const float* Ks = Stg + (jt & 1) * KV_STG;
        const float* Vs = Ks + FKT * KSP;

        // GEMM1: S[16x64] = Q @ K^T   (B-frag: Ks[(j8+g)*68 + ks8+tg])
        float sacc[8][4];
#pragma unroll
        for (int j = 0; j < 8; j++)
#pragma unroll
            for (int c = 0; c < 4; c++) sacc[j][c] = 0.f;

#pragma unroll
        for (int ks = 0; ks < 8; ks++) {
#pragma unroll
            for (int j = 0; j < 8; j++) {
                uint32_t bb[2];
                bb[0] = __float_as_uint(Ks[(j * 8 + g) * KSP + ks * 8 + tg    ]);
                bb[1] = __float_as_uint(Ks[(j * 8 + g) * KSP + ks * 8 + tg + 4]);
                mma_tf32(sacc[j], qa[ks], bb);
            }
        }

        // Max-free softmax numerator; tf32-round P; row sums via quad shuffle
        float rs0 = 0.f, rs1 = 0.f;
#pragma unroll
        for (int j = 0; j < 8; j++) {
            float p0 = tf32r(__expf(sacc[j][0]));
            float p1 = tf32r(__expf(sacc[j][1]));
            float p2 = tf32r(__expf(sacc[j][2]));
            float p3 = tf32r(__expf(sacc[j][3]));
            rs0 += p0 + p1;
            rs1 += p2 + p3;
            *(float2*)&QsPs[(m0 + g    ) * QP + j * 8 + 2 * tg] = make_float2(p0, p1);
            *(float2*)&QsPs[(m0 + g + 8) * QP + j * 8 + 2 * tg] = make_float2(p2, p3);
        }
        rs0 += __shfl_xor_sync(0xffffffffu, rs0, 1);
        rs0 += __shfl_xor_sync(0xffffffffu, rs0, 2);
        rs1 += __shfl_xor_sync(0xffffffffu, rs1, 1);
        rs1 += __shfl_xor_sync(0xffffffffu, rs1, 2);
        l0 += rs0;
        l1 += rs1;
        __syncwarp();   // Ps rows are warp-local

        // GEMM2: O += P @ V   (B-frag: Vs[(ks8+tg)*72 + j8+g])
#pragma unroll
        for (int ks = 0; ks < 8; ks++) {
            uint32_t a[4];
            a[0] = __float_as_uint(QsPs[(m0 + g    ) * QP + ks * 8 + tg    ]);
            a[1] = __float_as_uint(QsPs[(m0 + g + 8) * QP + ks * 8 + tg    ]);
            a[2] = __float_as_uint(QsPs[(m0 + g    ) * QP + ks * 8 + tg + 4]);
            a[3] = __float_as_uint(QsPs[(m0 + g + 8) * QP + ks * 8 + tg + 4]);
#pragma unroll
            for (int j = 0; j < 8; j++) {
                uint32_t bb[2];
                bb[0] = __float_as_uint(Vs[(ks * 8 + tg    ) * VSP + j * 8 + g]);
                bb[1] = __float_as_uint(Vs[(ks * 8 + tg + 4) * VSP + j * 8 + g]);
                mma_tf32(oacc[j], a, bb);
            }
        }
        __syncthreads();   // all warps done with this K/V stage before overwrite
    }

    // Epilogue: softmax divide + tf32 rounding (feeds final tf32 GEMM directly)
    float* obase = o + ((size_t)(b * SS) + qt * FQ) * DD + h * DHD;
    const float inv0 = 1.f / l0, inv1 = 1.f / l1;
#pragma unroll
    for (int j = 0; j < 8; j++) {
        const int col = j * 8 + 2 * tg;
        *(float2*)(obase + (size_t)(m0 + g    ) * DD + col) =
            make_float2(tf32r(oacc[j][0] * inv0), tf32r(oacc[j][1] * inv0));
        *(float2*)(obase + (size_t)(m0 + g + 8) * DD + col) =
            make_float2(tf32r(oacc[j][2] * inv1), tf32r(oacc[j][3] * inv1));
    }
}

// ---------------------------------------------------------------------------
extern "C" void kernel_launch(void* const* d_in, const int* in_sizes, int n_in,
                              void* d_out, int out_size)
{
    const float* x     = (const float*)d_in[0];
    const float* w_q   = (const float*)d_in[1];
    const float* w_kv  = (const float*)d_in[2];
    const float* w_out = (const float*)d_in[3];
    const float* b_out = (const float*)d_in[4];
    const float* scale = (const float*)d_in[5];
    float* out = (float*)d_out;

    float *px, *pq, *pkv, *po, *pwq, *pwkv, *pwo;
    cudaGetSymbolAddress((void**)&px,   g_x);
    cudaGetSymbolAddress((void**)&pq,   g_q);
    cudaGetSymbolAddress((void**)&pkv,  g_kv);
    cudaGetSymbolAddress((void**)&po,   g_o);
    cudaGetSymbolAddress((void**)&pwq,  g_wq);
    cudaGetSymbolAddress((void**)&pwkv, g_wkv);
    cudaGetSymbolAddress((void**)&pwo,  g_wo);

    cudaFuncSetAttribute(flash_mma, cudaFuncAttributeMaxDynamicSharedMemorySize, FLASH_SMEM);
    cudaFuncSetAttribute(mma_gemm, cudaFuncAttributeMaxDynamicSharedMemorySize, GEMM_SMEM);

    // tf32-round GEMM operands (unbiased rna rounding)
    const int T = 256;
    round_tf32<<<(MROWS * DD / 4 + T - 1) / T, T>>>(x, px, MROWS * DD / 4);
    round_tf32<<<(DD * DD / 4 + T - 1) / T, T>>>(w_q, pwq, DD * DD / 4);
    round_tf32<<<(2 * DD * DD / 4 + T - 1) / T, T>>>(w_kv, pwkv, 2 * DD * DD / 4);
    round_tf32<<<(DD * DD / 4 + T - 1) / T, T>>>(w_out, pwo, DD * DD / 4);

    // q = x @ w_q ; kv = x @ w_kv
    mma_gemm<<<dim3(DD / 128, MROWS / 128), 256, GEMM_SMEM>>>(px, pwq, pq, DD, DD, nullptr);
    mma_gemm<<<dim3(2 * DD / 128, MROWS / 128), 256, GEMM_SMEM>>>(px, pwkv, pkv, 2 * DD, DD, nullptr);

    // L2-normalize q (x exp(scale)) and k; tf32-round q, k, v
    normalize_kernel<<<(3 * MROWS * HH) / 8, 256>>>(pq, pkv, scale);

    // attention (tensor-core flash, epilogue pre-rounds to tf32)
    flash_mma<<<dim3(SS / FQ, HH, BB), 256, FLASH_SMEM>>>(pq, pkv, po);

    // out = g_o @ w_out + b_out
    mma_gemm<<<dim3(DD / 128, MROWS / 128), 256, GEMM_SMEM>>>(po, pwo, out, DD, DD, b_out);
}

// round 7
// speedup vs baseline: 2.9143x; 1.0350x over previous
#include <cuda_runtime.h>
#include <math.h>
#include <stdint.h>

// Problem constants: B=2, S=2048, D=1024, H=16, DH=64, INNER=1024
#define BB   2
#define SS   2048
#define DD   1024
#define HH   16
#define DHD  64
#define MROWS (BB * SS)   // 4096 token rows

// Scratch (static device globals -- no allocations allowed)
__device__ float g_x  [(size_t)MROWS * DD];         // tf32-rounded x
__device__ float g_q  [(size_t)MROWS * DD];         // q (normalized+scaled+rounded)
__device__ float g_kv [(size_t)MROWS * 2 * DD];     // [k(normalized) | v] rounded
__device__ float g_o  [(size_t)MROWS * DD];         // attention output (tf32-rounded)
__device__ float g_wq [(size_t)DD * DD];            // tf32-rounded w_q
__device__ float g_wkv[(size_t)DD * 2 * DD];        // tf32-rounded w_kv
__device__ float g_wo [(size_t)DD * DD];            // tf32-rounded w_out

// ---------------------------------------------------------------------------
// helpers
// ---------------------------------------------------------------------------
__device__ __forceinline__ uint32_t smem_u32(const void* p) {
    uint32_t a;
    asm("{ .reg .u64 t; cvta.to.shared.u64 t, %1; cvt.u32.u64 %0, t; }" : "=r"(a) : "l"(p));
    return a;
}

__device__ __forceinline__ float tf32r(float x) {
    uint32_t u;
    asm("cvt.rna.tf32.f32 %0, %1;" : "=r"(u) : "f"(x));
    return __uint_as_float(u);
}

__device__ __forceinline__ void cp16(uint32_t dst, const void* src) {
    asm volatile("cp.async.cg.shared.global [%0], [%1], 16;" :: "r"(dst), "l"(src));
}
__device__ __forceinline__ void cp_commit() {
    asm volatile("cp.async.commit_group;" ::: "memory");
}
__device__ __forceinline__ void cp_wait0() {
    asm volatile("cp.async.wait_group 0;" ::: "memory");
}

__device__ __forceinline__ void mma_tf32(float* d, const uint32_t* a, const uint32_t* b) {
    asm volatile(
        "mma.sync.aligned.m16n8k8.row.col.f32.tf32.tf32.f32 "
        "{%0,%1,%2,%3}, {%4,%5,%6,%7}, {%8,%9}, {%0,%1,%2,%3};"
        : "+f"(d[0]), "+f"(d[1]), "+f"(d[2]), "+f"(d[3])
        : "r"(a[0]), "r"(a[1]), "r"(a[2]), "r"(a[3]), "r"(b[0]), "r"(b[1]));
}

// ---------------------------------------------------------------------------
// tf32 rounding copy: n4 = element count / 4
// ---------------------------------------------------------------------------
__global__ void round_tf32(const float* __restrict__ in, float* __restrict__ out, int n4)
{
    int i = blockIdx.x * blockDim.x + threadIdx.x;
    if (i < n4) {
        float4 v = ((const float4*)in)[i];
        v.x = tf32r(v.x); v.y = tf32r(v.y); v.z = tf32r(v.z); v.w = tf32r(v.w);
        ((float4*)out)[i] = v;
    }
}

// ---------------------------------------------------------------------------
// tf32 mma.sync GEMM: C[M,N] = A[M,K] @ B[K,N]
// 128x128x32 CTA tile, 256 threads (8 warps, warp tile 32x64 = one head wide),
// cp.async 2-stage pipeline, SINGLE barrier per K-chunk.
// mode 0: plain (+bias).  mode 1: q epilogue (L2-normalize head rows *
// exp(scale[h]), tf32 round).  mode 2: kv epilogue (cols<DD: L2-normalize;
// cols>=DD: plain; all tf32 rounded).
// ---------------------------------------------------------------------------
#define GA_PITCH 36
#define GB_PITCH 136
#define GA_STG_F (128 * GA_PITCH)
#define GB_STG_F (32 * GB_PITCH)
#define GEMM_SMEM ((2 * GA_STG_F + 2 * GB_STG_F) * 4)

__global__ __launch_bounds__(256) void mma_gemm(
    const float* __restrict__ A, const float* __restrict__ B,
    float* __restrict__ C, int N, int K, const float* __restrict__ bias,
    int mode, const float* __restrict__ scale)
{
    extern __shared__ float smem[];
    float* sAf = smem;
    float* sBf = smem + 2 * GA_STG_F;
    const uint32_t sbase = smem_u32(smem);

    const int t    = threadIdx.x;
    const int wid  = t >> 5, lane = t & 31;
    const int g    = lane >> 2, tg = lane & 3;
    const int wm   = wid >> 1, wn = wid & 1;
    const int bm   = blockIdx.y * 128;
    const int bn   = blockIdx.x * 128;

    const float* Ag = A + (size_t)bm * K;
    const float* Bg = B + bn;

    const int arow = t >> 1,  acol = (t & 1) * 16;
    const int brow = t >> 3,  bcol = (t & 7) * 4;

    const int nk = K / 32;

    auto loadStage = [&](int s, int kt) {
        uint32_t ad = sbase + (uint32_t)(s * GA_STG_F + arow * GA_PITCH + acol) * 4u;
        const float* as = Ag + (size_t)arow * K + kt * 32 + acol;
#pragma unroll
        for (int u = 0; u < 4; u++) cp16(ad + u * 16, as + u * 4);
        uint32_t bd = sbase + (uint32_t)((2 * GA_STG_F) + s * GB_STG_F + brow * GB_PITCH + bcol) * 4u;
        const float* bs = Bg + (size_t)(kt * 32 + brow) * N + bcol;
#pragma unroll
        for (int u = 0; u < 4; u++) cp16(bd + u * 128, bs + u * 32);
    };

    float acc[2][8][4];
#pragma unroll
    for (int i = 0; i < 2; i++)
#pragma unroll
        for (int j = 0; j < 8; j++)
#pragma unroll
            for (int c = 0; c < 4; c++) acc[i][j][c] = 0.f;

    loadStage(0, 0);
    cp_commit();

    for (int kt = 0; kt < nk; kt++) {
        cp_wait0();        // own stage-kt copies done (prefetch had full overlap)
        __syncthreads();   // all warps' stage kt visible AND done reading kt-1

        if (kt + 1 < nk) {
            loadStage((kt + 1) & 1, kt + 1);   // safe: everyone left stage (kt+1)&1
            cp_commit();
        }

        const float* sa = sAf + (kt & 1) * GA_STG_F;
        const float* sb = sBf + (kt & 1) * GB_STG_F;

#pragma unroll
        for (int ks = 0; ks < 4; ks++) {
            uint32_t a[2][4];
#pragma unroll
            for (int i = 0; i < 2; i++) {
                const int row = wm * 32 + i * 16 + g;
                a[i][0] = __float_as_uint(sa[(row    ) * GA_PITCH + ks * 8 + tg    ]);
                a[i][1] = __float_as_uint(sa[(row + 8) * GA_PITCH + ks * 8 + tg    ]);
                a[i][2] = __float_as_uint(sa[(row    ) * GA_PITCH + ks * 8 + tg + 4]);
                a[i][3] = __float_as_uint(sa[(row + 8) * GA_PITCH + ks * 8 + tg + 4]);
            }
            uint32_t b[8][2];
#pragma unroll
            for (int j = 0; j < 8; j++) {
                const int col = wn * 64 + j * 8 + g;
                b[j][0] = __float_as_uint(sb[(ks * 8 + tg    ) * GB_PITCH + col]);
                b[j][1] = __float_as_uint(sb[(ks * 8 + tg + 4) * GB_PITCH + col]);
            }
#pragma unroll
            for (int i = 0; i < 2; i++)
#pragma unroll
                for (int j = 0; j < 8; j++)
                    mma_tf32(acc[i][j], a[i], b[j]);
        }
        // no trailing barrier: next-iter barrier protects stage reuse
    }

    // ---------------- epilogue ----------------
    const int colBase = bn + wn * 64;          // this warp's 64-col head block
    const bool doNorm = (mode == 1) || (mode == 2 && colBase < DD);

#pragma unroll
    for (int i = 0; i < 2; i++) {
        const int row = bm + wm * 32 + i * 16 + g;
        float f0 = 1.f, f1 = 1.f;
        if (doNorm) {
            float ss0 = 0.f, ss1 = 0.f;
#pragma unroll
            for (int j = 0; j < 8; j++) {
                ss0 += acc[i][j][0] * acc[i][j][0] + acc[i][j][1] * acc[i][j][1];
                ss1 += acc[i][j][2] * acc[i][j][2] + acc[i][j][3] * acc[i][j][3];
            }
            ss0 += __shfl_xor_sync(0xffffffffu, ss0, 1);
            ss0 += __shfl_xor_sync(0xffffffffu, ss0, 2);
            ss1 += __shfl_xor_sync(0xffffffffu, ss1, 1);
            ss1 += __shfl_xor_sync(0xffffffffu, ss1, 2);
            f0 = 1.f / fmaxf(sqrtf(ss0), 1e-12f);
            f1 = 1.f / fmaxf(sqrtf(ss1), 1e-12f);
            if (mode == 1) {
                const float e = expf(scale[colBase >> 6]);
                f0 *= e;
                f1 *= e;
            }
        }
#pragma unroll
        for (int j = 0; j < 8; j++) {
            const int col = colBase + j * 8 + tg * 2;
            float2 v0 = make_float2(acc[i][j][0] * f0, acc[i][j][1] * f0);
            float2 v1 = make_float2(acc[i][j][2] * f1, acc[i][j][3] * f1);
            if (mode == 0) {
                if (bias) {
                    float b0 = bias[col], b1 = bias[col + 1];
                    v0.x += b0; v0.y += b1;
                    v1.x += b0; v1.y += b1;
                }
            } else {
                v0.x = tf32r(v0.x); v0.y = tf32r(v0.y);
                v1.x = tf32r(v1.x); v1.y = tf32r(v1.y);
            }
            *(float2*)(C + (size_t)row * N + col)       = v0;
            *(float2*)(C + (size_t)(row + 8) * N + col) = v1;
        }
    }
}

// ---------------------------------------------------------------------------
// Flash attention, tf32 mma.sync, cp.async 2-stage K/V pipeline, Q fragments
// register-resident, Ps reuses the Qs smem region. SINGLE barrier per tile.
// CTA: 128 q-rows, 8 warps x 16 rows, 64-key tiles, 32 iterations.
// ---------------------------------------------------------------------------
#define FQ  128
#define FKT 64
#define QP  68
#define KSP 68
#define VSP 72
#define KV_STG (FKT * KSP + FKT * VSP)     // floats per stage (8960)
#define FLASH_SMEM ((FQ * QP + 2 * KV_STG) * 4)

__global__ __launch_bounds__(256) void flash_mma(
    const float* __restrict__ q, const float* __restrict__ kv, float* __restrict__ o)
{
    extern __shared__ float sm[];
    float* QsPs = sm;                          // [128][68] : Q in prologue, P after
    float* Stg  = sm + FQ * QP;
    const uint32_t sbase = smem_u32(sm);
    const uint32_t stgBase = sbase + FQ * QP * 4u;

    const int qt = blockIdx.x, h = blockIdx.y, b = blockIdx.z;
    const int tid = threadIdx.x, wid = tid >> 5, lane = tid & 31;
    const int g = lane >> 2, tg = lane & 3;
    const int m0 = wid * 16;

    const float* qbase = q  + ((size_t)(b * SS) + qt * FQ) * DD + h * DHD;
    const float* kbase = kv + (size_t)(b * SS) * (2 * DD) + h * DHD;
    const float* vbase = kbase + DD;

    const int sr = tid >> 2, sc = (tid & 3) * 16;

    auto prefetchKV = [&](int s, int jt) {
        const float* krow = kbase + (size_t)(jt * FKT + sr) * (2 * DD) + sc;
        const float* vrow = vbase + (size_t)(jt * FKT + sr) * (2 * DD) + sc;
        uint32_t kd = stgBase + (uint32_t)(s * KV_STG + sr * KSP + sc) * 4u;
        uint32_t vd = stgBase + (uint32_t)(s * KV_STG + FKT * KSP + sr * VSP + sc) * 4u;
#pragma unroll
        for (int u = 0; u < 4; u++) {
            cp16(kd + u * 16, krow + u * 4);
            cp16(vd + u * 16, vrow + u * 4);
        }
    };

    prefetchKV(0, 0);
    cp_commit();

    // Stage Q, hoist fragments to registers
    {
        const int r = tid >> 1, c0 = (tid & 1) * 32;
#pragma unroll
        for (int u = 0; u < 8; u++) {
            float4 v = *(const float4*)(qbase + (size_t)r * DD + c0 + u * 4);
            *(float4*)&QsPs[r * QP + c0 + u * 4] = v;
        }
    }
    __syncthreads();

    uint32_t qa[8][4];
#pragma unroll
    for (int ks = 0; ks < 8; ks++) {
        qa[ks][0] = __float_as_uint(QsPs[(m0 + g    ) * QP + ks * 8 + tg    ]);
        qa[ks][1] = __float_as_uint(QsPs[(m0 + g + 8) * QP + ks * 8 + tg    ]);
        qa[ks][2] = __float_as_uint(QsPs[(m0 + g    ) * QP + ks * 8 + tg + 4]);
        qa[ks][3] = __float_as_uint(QsPs[(m0 + g + 8) * QP + ks * 8 + tg + 4]);
    }

    float l0 = 0.f, l1 = 0.f;
    float oacc[8][4];
#pragma unroll
    for (int j = 0; j < 8; j++)
#pragma unroll
        for (int c = 0; c < 4; c++) oacc[j][c] = 0.f;

    const int NT = SS / FKT;
    for (int jt = 0; jt < NT; jt++) {
        cp_wait0();        // own stage-jt copies done
        __syncthreads();   // everyone's stage jt visible AND done with jt-1
                           // (also fences qa-loads vs first Ps write at jt=0)
        if (jt + 1 < NT) {
            prefetchKV((jt + 1) & 1, jt + 1);  // stage freed by the barrier
            cp_commit();
        }

        const float* Ks = Stg + (jt & 1) * KV_STG;
        const float* Vs = Ks + FKT * KSP;

        // GEMM1: S[16x64] = Q @ K^T
        float sacc[8][4];
#pragma unroll
        for (int j = 0; j < 8; j++)
#pragma unroll
            for (int c = 0; c < 4; c++) sacc[j][c] = 0.f;

#pragma unroll
        for (int ks = 0; ks < 8; ks++) {
#pragma unroll
            for (int j = 0; j < 8; j++) {
                uint32_t bb[2];
                bb[0] = __float_as_uint(Ks[(j * 8 + g) * KSP + ks * 8 + tg    ]);
                bb[1] = __float_as_uint(Ks[(j * 8 + g) * KSP + ks * 8 + tg + 4]);
                mma_tf32(sacc[j], qa[ks], bb);
            }
        }

        // Max-free softmax numerator (|logit| <= exp(scale) ~ 0.0455)
        float rs0 = 0.f, rs1 = 0.f;
#pragma unroll
        for (int j = 0; j < 8; j++) {
            float p0 = tf32r(__expf(sacc[j][0]));
            float p1 = tf32r(__expf(sacc[j][1]));
            float p2 = tf32r(__expf(sacc[j][2]));
            float p3 = tf32r(__expf(sacc[j][3]));
            rs0 += p0 + p1;
            rs1 += p2 + p3;
            *(float2*)&QsPs[(m0 + g    ) * QP + j * 8 + 2 * tg] = make_float2(p0, p1);
            *(float2*)&QsPs[(m0 + g + 8) * QP + j * 8 + 2 * tg] = make_float2(p2, p3);
        }
        rs0 += __shfl_xor_sync(0xffffffffu, rs0, 1);
        rs0 += __shfl_xor_sync(0xffffffffu, rs0, 2);
        rs1 += __shfl_xor_sync(0xffffffffu, rs1, 1);
        rs1 += __shfl_xor_sync(0xffffffffu, rs1, 2);
        l0 += rs0;
        l1 += rs1;
        __syncwarp();   // Ps rows are warp-local

        // GEMM2: O += P @ V
#pragma unroll
        for (int ks = 0; ks < 8; ks++) {
            uint32_t a[4];
            a[0] = __float_as_uint(QsPs[(m0 + g    ) * QP + ks * 8 + tg    ]);
            a[1] = __float_as_uint(QsPs[(m0 + g + 8) * QP + ks * 8 + tg    ]);
            a[2] = __float_as_uint(QsPs[(m0 + g    ) * QP + ks * 8 + tg + 4]);
            a[3] = __float_as_uint(QsPs[(m0 + g + 8) * QP + ks * 8 + tg + 4]);
#pragma unroll
            for (int j = 0; j < 8; j++) {
                uint32_t bb[2];
                bb[0] = __float_as_uint(Vs[(ks * 8 + tg    ) * VSP + j * 8 + g]);
                bb[1] = __float_as_uint(Vs[(ks * 8 + tg + 4) * VSP + j * 8 + g]);
                mma_tf32(oacc[j], a, bb);
            }
        }
        // no trailing barrier: next-iter barrier protects stage reuse
    }

    // Epilogue: softmax divide + tf32 round (feeds final tf32 GEMM)
    float* obase = o + ((size_t)(b * SS) + qt * FQ) * DD + h * DHD;
    const float inv0 = 1.f / l0, inv1 = 1.f / l1;
#pragma unroll
    for (int j = 0; j < 8; j++) {
        const int col = j * 8 + 2 * tg;
        *(float2*)(obase + (size_t)(m0 + g    ) * DD + col) =
            make_float2(tf32r(oacc[j][0] * inv0), tf32r(oacc[j][1] * inv0));
        *(float2*)(obase + (size_t)(m0 + g + 8) * DD + col) =
            make_float2(tf32r(oacc[j][2] * inv1), tf32r(oacc[j][3] * inv1));
    }
}

// ---------------------------------------------------------------------------
extern "C" void kernel_launch(void* const* d_in, const int* in_sizes, int n_in,
                              void* d_out, int out_size)
{
    const float* x     = (const float*)d_in[0];
    const float* w_q   = (const float*)d_in[1];
    const float* w_kv  = (const float*)d_in[2];
    const float* w_out = (const float*)d_in[3];
    const float* b_out = (const float*)d_in[4];
    const float* scale = (const float*)d_in[5];
    float* out = (float*)d_out;

    float *px, *pq, *pkv, *po, *pwq, *pwkv, *pwo;
    cudaGetSymbolAddress((void**)&px,   g_x);
    cudaGetSymbolAddress((void**)&pq,   g_q);
    cudaGetSymbolAddress((void**)&pkv,  g_kv);
    cudaGetSymbolAddress((void**)&po,   g_o);
    cudaGetSymbolAddress((void**)&pwq,  g_wq);
    cudaGetSymbolAddress((void**)&pwkv, g_wkv);
    cudaGetSymbolAddress((void**)&pwo,  g_wo);

    cudaFuncSetAttribute(flash_mma, cudaFuncAttributeMaxDynamicSharedMemorySize, FLASH_SMEM);
    cudaFuncSetAttribute(mma_gemm, cudaFuncAttributeMaxDynamicSharedMemorySize, GEMM_SMEM);

    // tf32-round GEMM operands (unbiased rna rounding)
    const int T = 256;
    round_tf32<<<(MROWS * DD / 4 + T - 1) / T, T>>>(x, px, MROWS * DD / 4);
    round_tf32<<<(DD * DD / 4 + T - 1) / T, T>>>(w_q, pwq, DD * DD / 4);
    round_tf32<<<(2 * DD * DD / 4 + T - 1) / T, T>>>(w_kv, pwkv, 2 * DD * DD / 4);
    round_tf32<<<(DD * DD / 4 + T - 1) / T, T>>>(w_out, pwo, DD * DD / 4);

    // q = l2norm(x @ w_q) * exp(scale), rounded  (mode 1, fused epilogue)
    mma_gemm<<<dim3(DD / 128, MROWS / 128), 256, GEMM_SMEM>>>(
        px, pwq, pq, DD, DD, nullptr, 1, scale);
    // kv = x @ w_kv; k half l2-normalized; all rounded  (mode 2)
    mma_gemm<<<dim3(2 * DD / 128, MROWS / 128), 256, GEMM_SMEM>>>(
        px, pwkv, pkv, 2 * DD, DD, nullptr, 2, nullptr);

    // attention (tensor-core flash, epilogue pre-rounds to tf32)
    flash_mma<<<dim3(SS / FQ, HH, BB), 256, FLASH_SMEM>>>(pq, pkv, po);

    // out = g_o @ w_out + b_out  (mode 0)
    mma_gemm<<<dim3(DD / 128, MROWS / 128), 256, GEMM_SMEM>>>(
        po, pwo, out, DD, DD, b_out, 0, nullptr);
}

// round 9
// speedup vs baseline: 2.9480x; 1.0116x over previous
#include <cuda_runtime.h>
#include <math.h>
#include <stdint.h>

// Problem constants: B=2, S=2048, D=1024, H=16, DH=64, INNER=1024
#define BB   2
#define SS   2048
#define DD   1024
#define HH   16
#define DHD  64
#define MROWS (BB * SS)   // 4096 token rows

// Scratch (static device globals -- no allocations allowed)
__device__ float g_x  [(size_t)MROWS * DD];         // tf32-rounded x
__device__ float g_q  [(size_t)MROWS * DD];         // q (normalized+scaled+rounded)
__device__ float g_kv [(size_t)MROWS * 2 * DD];     // [k(normalized) | v] rounded
__device__ float g_o  [(size_t)MROWS * DD];         // attention output (tf32-rounded)
__device__ float g_wq [(size_t)DD * DD];            // tf32-rounded w_q
__device__ float g_wkv[(size_t)DD * 2 * DD];        // tf32-rounded w_kv
__device__ float g_wo [(size_t)DD * DD];            // tf32-rounded w_out

// ---------------------------------------------------------------------------
// helpers
// ---------------------------------------------------------------------------
__device__ __forceinline__ uint32_t smem_u32(const void* p) {
    uint32_t a;
    asm("{ .reg .u64 t; cvta.to.shared.u64 t, %1; cvt.u32.u64 %0, t; }" : "=r"(a) : "l"(p));
    return a;
}

__device__ __forceinline__ float tf32r(float x) {
    uint32_t u;
    asm("cvt.rna.tf32.f32 %0, %1;" : "=r"(u) : "f"(x));
    return __uint_as_float(u);
}

__device__ __forceinline__ void cp16(uint32_t dst, const void* src) {
    asm volatile("cp.async.cg.shared.global [%0], [%1], 16;" :: "r"(dst), "l"(src));
}
__device__ __forceinline__ void cp_commit() {
    asm volatile("cp.async.commit_group;" ::: "memory");
}
__device__ __forceinline__ void cp_wait0() {
    asm volatile("cp.async.wait_group 0;" ::: "memory");
}

__device__ __forceinline__ void mma_tf32(float* d, const uint32_t* a, const uint32_t* b) {
    asm volatile(
        "mma.sync.aligned.m16n8k8.row.col.f32.tf32.tf32.f32 "
        "{%0,%1,%2,%3}, {%4,%5,%6,%7}, {%8,%9}, {%0,%1,%2,%3};"
        : "+f"(d[0]), "+f"(d[1]), "+f"(d[2]), "+f"(d[3])
        : "r"(a[0]), "r"(a[1]), "r"(a[2]), "r"(a[3]), "r"(b[0]), "r"(b[1]));
}

// ldmatrix x4 (b16 view of tf32 data): loads 4 m8n8-b16 matrices = 4 b32 regs
__device__ __forceinline__ void ldm_x4(uint32_t* r, uint32_t addr) {
    asm volatile("ldmatrix.sync.aligned.m8n8.x4.shared.b16 {%0,%1,%2,%3}, [%4];"
        : "=r"(r[0]), "=r"(r[1]), "=r"(r[2]), "=r"(r[3]) : "r"(addr));
}

// ---------------------------------------------------------------------------
// tf32 rounding kernels
// ---------------------------------------------------------------------------
__global__ void round_tf32(const float* __restrict__ in, float* __restrict__ out, int n4)
{
    int i = blockIdx.x * blockDim.x + threadIdx.x;
    if (i < n4) {
        float4 v = ((const float4*)in)[i];
        v.x = tf32r(v.x); v.y = tf32r(v.y); v.z = tf32r(v.z); v.w = tf32r(v.w);
        ((float4*)out)[i] = v;
    }
}

// all three weights in one launch
#define WQ4  (DD * DD / 4)
#define WKV4 (2 * DD * DD / 4)
__global__ void round_w(const float* __restrict__ wq,  float* __restrict__ owq,
                        const float* __restrict__ wkv, float* __restrict__ owkv,
                        const float* __restrict__ wo,  float* __restrict__ owo)
{
    int i = blockIdx.x * blockDim.x + threadIdx.x;
    const float4* src;
    float4* dst;
    int idx;
    if (i < WQ4)             { src = (const float4*)wq;  dst = (float4*)owq;  idx = i; }
    else if (i < WQ4 + WKV4) { src = (const float4*)wkv; dst = (float4*)owkv; idx = i - WQ4; }
    else                     { src = (const float4*)wo;  dst = (float4*)owo;  idx = i - WQ4 - WKV4; }
    float4 v = src[idx];
    v.x = tf32r(v.x); v.y = tf32r(v.y); v.z = tf32r(v.z); v.w = tf32r(v.w);
    dst[idx] = v;
}

// ---------------------------------------------------------------------------
// tf32 mma.sync GEMM: C[M,N] = A[M,K] @ B[K,N]
// 128x128x32 CTA tile, 256 threads, cp.async 2-stage pipeline, single barrier
// per chunk, ldmatrix A-fragments.
// mode 0: plain (+bias). mode 1: q epilogue (L2-norm rows * exp(scale), round).
// mode 2: kv epilogue (cols<DD normalized; all rounded).
// ---------------------------------------------------------------------------
#define GA_PITCH 36
#define GB_PITCH 136
#define GA_STG_F (128 * GA_PITCH)
#define GB_STG_F (32 * GB_PITCH)
#define GEMM_SMEM ((2 * GA_STG_F + 2 * GB_STG_F) * 4)

__global__ __launch_bounds__(256) void mma_gemm(
    const float* __restrict__ A, const float* __restrict__ B,
    float* __restrict__ C, int N, int K, const float* __restrict__ bias,
    int mode, const float* __restrict__ scale)
{
    extern __shared__ float smem[];
    float* sBf = smem + 2 * GA_STG_F;
    const uint32_t sbase = smem_u32(smem);

    const int t    = threadIdx.x;
    const int wid  = t >> 5, lane = t & 31;
    const int g    = lane >> 2, tg = lane & 3;
    const int wm   = wid >> 1, wn = wid & 1;
    const int bm   = blockIdx.y * 128;
    const int bn   = blockIdx.x * 128;

    const float* Ag = A + (size_t)bm * K;
    const float* Bg = B + bn;

    const int arow = t >> 1,  acol = (t & 1) * 16;
    const int brow = t >> 3,  bcol = (t & 7) * 4;

    // ldmatrix A-pattern: row = (l%8) + 8*((l>>3)&1), b32col = 4*(l>>4)
    const uint32_t a_lm = (uint32_t)(((lane & 7) + 8 * ((lane >> 3) & 1)) * GA_PITCH * 4
                                     + (lane >> 4) * 16);

    const int nk = K / 32;

    auto loadStage = [&](int s, int kt) {
        uint32_t ad = sbase + (uint32_t)(s * GA_STG_F + arow * GA_PITCH + acol) * 4u;
        const float* as = Ag + (size_t)arow * K + kt * 32 + acol;
#pragma unroll
        for (int u = 0; u < 4; u++) cp16(ad + u * 16, as + u * 4);
        uint32_t bd = sbase + (uint32_t)((2 * GA_STG_F) + s * GB_STG_F + brow * GB_PITCH + bcol) * 4u;
        const float* bs = Bg + (size_t)(kt * 32 + brow) * N + bcol;
#pragma unroll
        for (int u = 0; u < 4; u++) cp16(bd + u * 128, bs + u * 32);
    };

    float acc[2][8][4];
#pragma unroll
    for (int i = 0; i < 2; i++)
#pragma unroll
        for (int j = 0; j < 8; j++)
#pragma unroll
            for (int c = 0; c < 4; c++) acc[i][j][c] = 0.f;

    loadStage(0, 0);
    cp_commit();

    for (int kt = 0; kt < nk; kt++) {
        cp_wait0();
        __syncthreads();

        if (kt + 1 < nk) {
            loadStage((kt + 1) & 1, kt + 1);
            cp_commit();
        }

        const uint32_t saA = sbase + (uint32_t)((kt & 1) * GA_STG_F) * 4u
                           + (uint32_t)(wm * 32 * GA_PITCH) * 4u + a_lm;
        const float* sb = sBf + (kt & 1) * GB_STG_F;

#pragma unroll
        for (int ks = 0; ks < 4; ks++) {
            uint32_t a[2][4];
            ldm_x4(a[0], saA + ks * 32);
            ldm_x4(a[1], saA + 16 * GA_PITCH * 4 + ks * 32);
            uint32_t b[8][2];
#pragma unroll
            for (int j = 0; j < 8; j++) {
                const int col = wn * 64 + j * 8 + g;
                b[j][0] = __float_as_uint(sb[(ks * 8 + tg    ) * GB_PITCH + col]);
                b[j][1] = __float_as_uint(sb[(ks * 8 + tg + 4) * GB_PITCH + col]);
            }
#pragma unroll
            for (int i = 0; i < 2; i++)
#pragma unroll
                for (int j = 0; j < 8; j++)
                    mma_tf32(acc[i][j], a[i], b[j]);
        }
    }

    // ---------------- epilogue ----------------
    const int colBase = bn + wn * 64;
    const bool doNorm = (mode == 1) || (mode == 2 && colBase < DD);

#pragma unroll
    for (int i = 0; i < 2; i++) {
        const int row = bm + wm * 32 + i * 16 + g;
        float f0 = 1.f, f1 = 1.f;
        if (doNorm) {
            float ss0 = 0.f, ss1 = 0.f;
#pragma unroll
            for (int j = 0; j < 8; j++) {
                ss0 += acc[i][j][0] * acc[i][j][0] + acc[i][j][1] * acc[i][j][1];
                ss1 += acc[i][j][2] * acc[i][j][2] + acc[i][j][3] * acc[i][j][3];
            }
            ss0 += __shfl_xor_sync(0xffffffffu, ss0, 1);
            ss0 += __shfl_xor_sync(0xffffffffu, ss0, 2);
            ss1 += __shfl_xor_sync(0xffffffffu, ss1, 1);
            ss1 += __shfl_xor_sync(0xffffffffu, ss1, 2);
            f0 = 1.f / fmaxf(sqrtf(ss0), 1e-12f);
            f1 = 1.f / fmaxf(sqrtf(ss1), 1e-12f);
            if (mode == 1) {
                const float e = expf(scale[colBase >> 6]);
                f0 *= e;
                f1 *= e;
            }
        }
#pragma unroll
        for (int j = 0; j < 8; j++) {
            const int col = colBase + j * 8 + tg * 2;
            float2 v0 = make_float2(acc[i][j][0] * f0, acc[i][j][1] * f0);
            float2 v1 = make_float2(acc[i][j][2] * f1, acc[i][j][3] * f1);
            if (mode == 0) {
                if (bias) {
                    float b0 = bias[col], b1 = bias[col + 1];
                    v0.x += b0; v0.y += b1;
                    v1.x += b0; v1.y += b1;
                }
            } else {
                v0.x = tf32r(v0.x); v0.y = tf32r(v0.y);
                v1.x = tf32r(v1.x); v1.y = tf32r(v1.y);
            }
            *(float2*)(C + (size_t)row * N + col)       = v0;
            *(float2*)(C + (size_t)(row + 8) * N + col) = v1;
        }
    }
}

// ---------------------------------------------------------------------------
// Flash attention, tf32 mma.sync + ldmatrix fragment loads.
// CTA: 128 q-rows, 8 warps x 16 rows, 64-key tiles, cp.async 2-stage K/V.
// GEMM1 B via ldmatrix x4 tiled along k: 8 n-rows x 16 k-floats per load ->
// per-pair byte offset p*64 (NOT p*32 -- that was the R7 bug).
// ---------------------------------------------------------------------------
#define FQ  128
#define FKT 64
#define QP  68
#define KSP 68
#define VSP 72
#define KV_STG (FKT * KSP + FKT * VSP)
#define FLASH_SMEM ((FQ * QP + 2 * KV_STG) * 4)

__global__ __launch_bounds__(256) void flash_mma(
    const float* __restrict__ q, const float* __restrict__ kv, float* __restrict__ o)
{
    extern __shared__ float sm[];
    float* QsPs = sm;                          // [128][68] : Q in prologue, P after
    const uint32_t sbase = smem_u32(sm);
    const uint32_t stgBase = sbase + FQ * QP * 4u;

    const int qt = blockIdx.x, h = blockIdx.y, b = blockIdx.z;
    const int tid = threadIdx.x, wid = tid >> 5, lane = tid & 31;
    const int g = lane >> 2, tg = lane & 3;
    const int m0 = wid * 16;

    const float* qbase = q  + ((size_t)(b * SS) + qt * FQ) * DD + h * DHD;
    const float* kbase = kv + (size_t)(b * SS) * (2 * DD) + h * DHD;
    const float* vbase = kbase + DD;

    const int sr = tid >> 2, sc = (tid & 3) * 16;

    // ldmatrix lane offsets
    // A-pattern (Q/Ps): row = (l%8)+8*((l>>3)&1), b32col = 4*(l>>4)
    const uint32_t a_lm = (uint32_t)(((lane & 7) + 8 * ((lane >> 3) & 1)) * QP * 4
                                     + (lane >> 4) * 16);
    // B-pattern (Ks): n-row = l%8, k-b32col = 4*(l>>3)  (4 matrices along k)
    const uint32_t b_lm = (uint32_t)((lane & 7) * KSP * 4 + (lane >> 3) * 16);

    auto prefetchKV = [&](int s, int jt) {
        const float* krow = kbase + (size_t)(jt * FKT + sr) * (2 * DD) + sc;
        const float* vrow = vbase + (size_t)(jt * FKT + sr) * (2 * DD) + sc;
        uint32_t kd = stgBase + (uint32_t)(s * KV_STG + sr * KSP + sc) * 4u;
        uint32_t vd = stgBase + (uint32_t)(s * KV_STG + FKT * KSP + sr * VSP + sc) * 4u;
#pragma unroll
        for (int u = 0; u < 4; u++) {
            cp16(kd + u * 16, krow + u * 4);
            cp16(vd + u * 16, vrow + u * 4);
        }
    };

    prefetchKV(0, 0);
    cp_commit();

    // Stage Q, hoist fragments via ldmatrix
    {
        const int r = tid >> 1, c0 = (tid & 1) * 32;
#pragma unroll
        for (int u = 0; u < 8; u++) {
            float4 v = *(const float4*)(qbase + (size_t)r * DD + c0 + u * 4);
            *(float4*)&QsPs[r * QP + c0 + u * 4] = v;
        }
    }
    __syncthreads();

    const uint32_t qpAddr = sbase + (uint32_t)(m0 * QP) * 4u + a_lm;
    uint32_t qa[8][4];
#pragma unroll
    for (int ks = 0; ks < 8; ks++) ldm_x4(qa[ks], qpAddr + ks * 32);

    float l0 = 0.f, l1 = 0.f;
    float oacc[8][4];
#pragma unroll
    for (int j = 0; j < 8; j++)
#pragma unroll
        for (int c = 0; c < 4; c++) oacc[j][c] = 0.f;

    const int NT = SS / FKT;
    for (int jt = 0; jt < NT; jt++) {
        cp_wait0();
        __syncthreads();   // stage jt visible; everyone done with jt-1 and
                           // (at jt=0) done loading qa before Ps overwrites

        if (jt + 1 < NT) {
            prefetchKV((jt + 1) & 1, jt + 1);
            cp_commit();
        }

        const uint32_t ksAddr = stgBase + (uint32_t)((jt & 1) * KV_STG) * 4u + b_lm;
        const float* Vs = sm + FQ * QP + (jt & 1) * KV_STG + FKT * KSP;

        // GEMM1: S[16x64] = Q @ K^T
        float sacc[8][4];
#pragma unroll
        for (int j = 0; j < 8; j++)
#pragma unroll
            for (int c = 0; c < 4; c++) sacc[j][c] = 0.f;

#pragma unroll
        for (int p = 0; p < 4; p++) {         // ks pairs (2p, 2p+1): k floats 16p..16p+15
#pragma unroll
            for (int j = 0; j < 8; j++) {
                uint32_t r[4];
                ldm_x4(r, ksAddr + (uint32_t)(j * 8 * KSP) * 4u + p * 64);
                mma_tf32(sacc[j], qa[2 * p],     r);       // matrices 0,1: k 16p..16p+7
                mma_tf32(sacc[j], qa[2 * p + 1], r + 2);   // matrices 2,3: k 16p+8..16p+15
            }
        }

        // Max-free softmax numerator (|logit| <= exp(scale) ~ 0.0455)
        float rs0 = 0.f, rs1 = 0.f;
#pragma unroll
        for (int j = 0; j < 8; j++) {
            float p0 = tf32r(__expf(sacc[j][0]));
            float p1 = tf32r(__expf(sacc[j][1]));
            float p2 = tf32r(__expf(sacc[j][2]));
            float p3 = tf32r(__expf(sacc[j][3]));
            rs0 += p0 + p1;
            rs1 += p2 + p3;
            *(float2*)&QsPs[(m0 + g    ) * QP + j * 8 + 2 * tg] = make_float2(p0, p1);
            *(float2*)&QsPs[(m0 + g + 8) * QP + j * 8 + 2 * tg] = make_float2(p2, p3);
        }
        rs0 += __shfl_xor_sync(0xffffffffu, rs0, 1);
        rs0 += __shfl_xor_sync(0xffffffffu, rs0, 2);
        rs1 += __shfl_xor_sync(0xffffffffu, rs1, 1);
        rs1 += __shfl_xor_sync(0xffffffffu, rs1, 2);
        l0 += rs0;
        l1 += rs1;
        __syncwarp();   // Ps rows are warp-local

        // GEMM2: O += P @ V  (A-frags via ldmatrix; V-frags scalar, k-major)
#pragma unroll
        for (int ks = 0; ks < 8; ks++) {
            uint32_t a[4];
            ldm_x4(a, qpAddr + ks * 32);
#pragma unroll
            for (int j = 0; j < 8; j++) {
                uint32_t bb[2];
                bb[0] = __float_as_uint(Vs[(ks * 8 + tg    ) * VSP + j * 8 + g]);
                bb[1] = __float_as_uint(Vs[(ks * 8 + tg + 4) * VSP + j * 8 + g]);
                mma_tf32(oacc[j], a, bb);
            }
        }
        // no trailing barrier: next-iter barrier protects stage reuse
    }

    // Epilogue: softmax divide + tf32 round (feeds final tf32 GEMM)
    float* obase = o + ((size_t)(b * SS) + qt * FQ) * DD + h * DHD;
    const float inv0 = 1.f / l0, inv1 = 1.f / l1;
#pragma unroll
    for (int j = 0; j < 8; j++) {
        const int col = j * 8 + 2 * tg;
        *(float2*)(obase + (size_t)(m0 + g    ) * DD + col) =
            make_float2(tf32r(oacc[j][0] * inv0), tf32r(oacc[j][1] * inv0));
        *(float2*)(obase + (size_t)(m0 + g + 8) * DD + col) =
            make_float2(tf32r(oacc[j][2] * inv1), tf32r(oacc[j][3] * inv1));
    }
}

// ---------------------------------------------------------------------------
extern "C" void kernel_launch(void* const* d_in, const int* in_sizes, int n_in,
                              void* d_out, int out_size)
{
    const float* x     = (const float*)d_in[0];
    const float* w_q   = (const float*)d_in[1];
    const float* w_kv  = (const float*)d_in[2];
    const float* w_out = (const float*)d_in[3];
    const float* b_out = (const float*)d_in[4];
    const float* scale = (const float*)d_in[5];
    float* out = (float*)d_out;

    float *px, *pq, *pkv, *po, *pwq, *pwkv, *pwo;
    cudaGetSymbolAddress((void**)&px,   g_x);
    cudaGetSymbolAddress((void**)&pq,   g_q);
    cudaGetSymbolAddress((void**)&pkv,  g_kv);
    cudaGetSymbolAddress((void**)&po,   g_o);
    cudaGetSymbolAddress((void**)&pwq,  g_wq);
    cudaGetSymbolAddress((void**)&pwkv, g_wkv);
    cudaGetSymbolAddress((void**)&pwo,  g_wo);

    cudaFuncSetAttribute(flash_mma, cudaFuncAttributeMaxDynamicSharedMemorySize, FLASH_SMEM);
    cudaFuncSetAttribute(mma_gemm, cudaFuncAttributeMaxDynamicSharedMemorySize, GEMM_SMEM);

    const int T = 256;
    // launch 0: round x
    round_tf32<<<(MROWS * DD / 4 + T - 1) / T, T>>>(x, px, MROWS * DD / 4);
    // launch 1: round all weights (merged)
    round_w<<<(WQ4 + WKV4 + WQ4 + T - 1) / T, T>>>(w_q, pwq, w_kv, pwkv, w_out, pwo);

    // launch 2: q = l2norm(x @ w_q) * exp(scale), rounded
    mma_gemm<<<dim3(DD / 128, MROWS / 128), 256, GEMM_SMEM>>>(
        px, pwq, pq, DD, DD, nullptr, 1, scale);
    // launch 3: kv = x @ w_kv; k half normalized; all rounded
    mma_gemm<<<dim3(2 * DD / 128, MROWS / 128), 256, GEMM_SMEM>>>(
        px, pwkv, pkv, 2 * DD, DD, nullptr, 2, nullptr);

    // launch 4: attention
    flash_mma<<<dim3(SS / FQ, HH, BB), 256, FLASH_SMEM>>>(pq, pkv, po);

    // launch 5: out = g_o @ w_out + b_out
    mma_gemm<<<dim3(DD / 128, MROWS / 128), 256, GEMM_SMEM>>>(
        po, pwo, out, DD, DD, b_out, 0, nullptr);
}